// round 1
// baseline (speedup 1.0000x reference)
#include <cuda_runtime.h>
#include <math.h>

#define E_DIM 1280
#define NHEAD 20
#define DHEAD 64
#define T_TOK 8192
#define SEQ   1024
#define NBATCH 8

// ---------------- scratch (no allocations allowed) ----------------
__device__ float g_h[T_TOK * E_DIM];
__device__ float g_q[T_TOK * E_DIM];
__device__ float g_k[T_TOK * E_DIM];
__device__ float g_v[T_TOK * E_DIM];
__device__ float g_o[T_TOK * E_DIM];

// ---------------- LayerNorm (with bias) : x -> h -------------------
__global__ void __launch_bounds__(256) ln_kernel(
    const float* __restrict__ x, const float* __restrict__ w,
    const float* __restrict__ b, float* __restrict__ out)
{
    int t = blockIdx.x;
    const float* xr = x + (size_t)t * E_DIM;
    float vals[5];
    float s = 0.f, s2 = 0.f;
#pragma unroll
    for (int j = 0; j < 5; j++) {
        float v = xr[threadIdx.x + j * 256];
        vals[j] = v; s += v; s2 += v * v;
    }
    // block reduce (8 warps)
    __shared__ float red0[8], red1[8];
    int lane = threadIdx.x & 31, wid = threadIdx.x >> 5;
#pragma unroll
    for (int o = 16; o; o >>= 1) {
        s  += __shfl_xor_sync(0xffffffffu, s,  o);
        s2 += __shfl_xor_sync(0xffffffffu, s2, o);
    }
    if (lane == 0) { red0[wid] = s; red1[wid] = s2; }
    __syncthreads();
    float ts = 0.f, ts2 = 0.f;
#pragma unroll
    for (int j = 0; j < 8; j++) { ts += red0[j]; ts2 += red1[j]; }
    float mean = ts * (1.f / E_DIM);
    float var  = ts2 * (1.f / E_DIM) - mean * mean;
    float rstd = rsqrtf(var + 1e-5f);
    float* orow = out + (size_t)t * E_DIM;
#pragma unroll
    for (int j = 0; j < 5; j++) {
        int idx = threadIdx.x + j * 256;
        orow[idx] = (vals[j] - mean) * rstd * w[idx] + b[idx];
    }
}

// ------------- LayerNorm (no bias) + RoPE, in place on q and k -----
__global__ void __launch_bounds__(256) lnrope_kernel(
    float* __restrict__ q, float* __restrict__ k,
    const float* __restrict__ wq, const float* __restrict__ wk,
    const int* __restrict__ cu, int nb)
{
    int t = blockIdx.x;
    __shared__ float sb[E_DIM];
    __shared__ float red0[8], red1[8];
    __shared__ float s_stats[2];
    int lane = threadIdx.x & 31, wid = threadIdx.x >> 5;

    // position within sequence
    int seg = 0;
    for (int bb = 1; bb < nb; bb++) if (t >= cu[bb]) seg = bb;
    float pos = (float)(t - cu[seg]);
    const float kfreq = -0.2878231366f; // -ln(10000)/32

    for (int part = 0; part < 2; part++) {
        float* base = (part ? k : q) + (size_t)t * E_DIM;
        const float* w = part ? wk : wq;
        float s = 0.f, s2 = 0.f;
        for (int i = threadIdx.x; i < E_DIM; i += 256) {
            float v = base[i];
            sb[i] = v; s += v; s2 += v * v;
        }
#pragma unroll
        for (int o = 16; o; o >>= 1) {
            s  += __shfl_xor_sync(0xffffffffu, s,  o);
            s2 += __shfl_xor_sync(0xffffffffu, s2, o);
        }
        if (lane == 0) { red0[wid] = s; red1[wid] = s2; }
        __syncthreads();
        if (threadIdx.x == 0) {
            float ts = 0.f, ts2 = 0.f;
#pragma unroll
            for (int j = 0; j < 8; j++) { ts += red0[j]; ts2 += red1[j]; }
            float mean = ts * (1.f / E_DIM);
            float var  = ts2 * (1.f / E_DIM) - mean * mean;
            s_stats[0] = mean;
            s_stats[1] = rsqrtf(var + 1e-5f);
        }
        __syncthreads();
        float mean = s_stats[0], rstd = s_stats[1];
        for (int i = threadIdx.x; i < E_DIM; i += 256) {
            int ld = i & 63;
            float xn = (sb[i] - mean) * rstd * w[i];
            int pi = (ld < 32) ? (i + 32) : (i - 32);
            float pn = (sb[pi] - mean) * rstd * w[pi];
            int fi = ld & 31;
            float ang = pos * __expf((float)fi * kfreq);
            float sn, c;
            sincosf(ang, &sn, &c);
            float rot = (ld < 32) ? -pn : pn;
            base[i] = xn * c + rot * sn;
        }
        __syncthreads();
    }
}

// ------------- SGEMM: C[m,n] = sum_k A[m,k] * B[n,k] ---------------
// BM=128, BN=128, BK=16, 256 threads, 8x8 microtile.
__global__ void __launch_bounds__(256) sgemm_nt(
    const float* __restrict__ A, const float* __restrict__ B,
    float* __restrict__ C, int M, int N, int K)
{
    const int BK = 16;
    __shared__ float As[BK][128];
    __shared__ float Bs[BK][128];
    int bm = blockIdx.y * 128, bn = blockIdx.x * 128;
    int tid = threadIdx.x;
    int tr = (tid >> 4) << 3;   // 0..120 step 8
    int tc = (tid & 15) << 3;

    float acc[8][8];
#pragma unroll
    for (int i = 0; i < 8; i++)
#pragma unroll
        for (int j = 0; j < 8; j++) acc[i][j] = 0.f;

    for (int k0 = 0; k0 < K; k0 += BK) {
#pragma unroll
        for (int i = 0; i < 2; i++) {
            int idx = tid + i * 256;      // 0..511 float4 loads
            int r  = idx >> 2;            // 0..127
            int c  = (idx & 3) << 2;      // 0,4,8,12
            float4 a = *(const float4*)&A[(size_t)(bm + r) * K + k0 + c];
            As[c + 0][r] = a.x; As[c + 1][r] = a.y;
            As[c + 2][r] = a.z; As[c + 3][r] = a.w;
            float4 bb = *(const float4*)&B[(size_t)(bn + r) * K + k0 + c];
            Bs[c + 0][r] = bb.x; Bs[c + 1][r] = bb.y;
            Bs[c + 2][r] = bb.z; Bs[c + 3][r] = bb.w;
        }
        __syncthreads();
#pragma unroll
        for (int k = 0; k < BK; k++) {
            float4 a0 = *(const float4*)&As[k][tr];
            float4 a1 = *(const float4*)&As[k][tr + 4];
            float4 b0 = *(const float4*)&Bs[k][tc];
            float4 b1 = *(const float4*)&Bs[k][tc + 4];
            float ra[8] = {a0.x, a0.y, a0.z, a0.w, a1.x, a1.y, a1.z, a1.w};
            float rb[8] = {b0.x, b0.y, b0.z, b0.w, b1.x, b1.y, b1.z, b1.w};
#pragma unroll
            for (int i = 0; i < 8; i++)
#pragma unroll
                for (int j = 0; j < 8; j++)
                    acc[i][j] = fmaf(ra[i], rb[j], acc[i][j]);
        }
        __syncthreads();
    }
#pragma unroll
    for (int i = 0; i < 8; i++) {
#pragma unroll
        for (int j = 0; j < 8; j += 4) {
            float4 vv = make_float4(acc[i][j], acc[i][j+1], acc[i][j+2], acc[i][j+3]);
            *(float4*)&C[(size_t)(bm + tr + i) * N + bn + tc + j] = vv;
        }
    }
}

// ------------- flash attention, fp32, 32x64 score tiles ------------
// grid: (S/32, H, B), 256 threads. Each thread: 2 rows x 4 cols microtile.
__global__ void __launch_bounds__(256) attn_kernel(
    const float* __restrict__ q, const float* __restrict__ k,
    const float* __restrict__ v, float* __restrict__ o)
{
    __shared__ float Qs[32 * 64];
    __shared__ float Ks[64 * 64];
    __shared__ float Vs[64 * 64];
    __shared__ float Ps[32 * 64];

    int b = blockIdx.z, h = blockIdx.y, qt = blockIdx.x;
    int tid = threadIdx.x;
    int tq0 = b * SEQ + qt * 32;

    // load Q tile (32x64) : 512 float4
    for (int i = tid; i < 512; i += 256) {
        int r = i >> 4, c4 = i & 15;
        *(float4*)&Qs[r * 64 + c4 * 4] =
            *(const float4*)&q[(size_t)(tq0 + r) * E_DIM + h * 64 + c4 * 4];
    }

    int rg = tid >> 4;       // 0..15 -> rows rg*2, rg*2+1
    int cg = tid & 15;       // 0..15 -> cols cg*4..cg*4+3 / dims cg*4..
    float m0 = -1e30f, m1 = -1e30f;
    float l0 = 0.f, l1 = 0.f;
    float oa0[4] = {0,0,0,0}, oa1[4] = {0,0,0,0};

    for (int kt = 0; kt < SEQ / 64; kt++) {
        __syncthreads();
        int tk0 = b * SEQ + kt * 64;
        for (int i = tid; i < 1024; i += 256) {
            int r = i >> 4, c4 = i & 15;
            *(float4*)&Ks[r * 64 + c4 * 4] =
                *(const float4*)&k[(size_t)(tk0 + r) * E_DIM + h * 64 + c4 * 4];
            *(float4*)&Vs[r * 64 + c4 * 4] =
                *(const float4*)&v[(size_t)(tk0 + r) * E_DIM + h * 64 + c4 * 4];
        }
        __syncthreads();

        // scores: s[2][4]
        float s00=0,s01=0,s02=0,s03=0, s10=0,s11=0,s12=0,s13=0;
#pragma unroll
        for (int d = 0; d < 64; d += 4) {
            float4 qa0 = *(const float4*)&Qs[(rg*2+0)*64 + d];
            float4 qa1 = *(const float4*)&Qs[(rg*2+1)*64 + d];
#define KDOT(J, ACC0, ACC1) { \
            float4 kb = *(const float4*)&Ks[(cg*4+J)*64 + d]; \
            ACC0 += qa0.x*kb.x + qa0.y*kb.y + qa0.z*kb.z + qa0.w*kb.w; \
            ACC1 += qa1.x*kb.x + qa1.y*kb.y + qa1.z*kb.z + qa1.w*kb.w; }
            KDOT(0, s00, s10) KDOT(1, s01, s11) KDOT(2, s02, s12) KDOT(3, s03, s13)
#undef KDOT
        }
        const float sc = 0.125f; // 64^-0.5
        s00*=sc; s01*=sc; s02*=sc; s03*=sc;
        s10*=sc; s11*=sc; s12*=sc; s13*=sc;

        // row max over 16 threads (consecutive lanes within half-warp)
        float tm0 = fmaxf(fmaxf(s00, s01), fmaxf(s02, s03));
        float tm1 = fmaxf(fmaxf(s10, s11), fmaxf(s12, s13));
#pragma unroll
        for (int off = 1; off < 16; off <<= 1) {
            tm0 = fmaxf(tm0, __shfl_xor_sync(0xffffffffu, tm0, off));
            tm1 = fmaxf(tm1, __shfl_xor_sync(0xffffffffu, tm1, off));
        }
        float mn0 = fmaxf(m0, tm0), mn1 = fmaxf(m1, tm1);
        float cor0 = __expf(m0 - mn0), cor1 = __expf(m1 - mn1);
        float p00=__expf(s00-mn0), p01=__expf(s01-mn0), p02=__expf(s02-mn0), p03=__expf(s03-mn0);
        float p10=__expf(s10-mn1), p11=__expf(s11-mn1), p12=__expf(s12-mn1), p13=__expf(s13-mn1);
        *(float4*)&Ps[(rg*2+0)*64 + cg*4] = make_float4(p00, p01, p02, p03);
        *(float4*)&Ps[(rg*2+1)*64 + cg*4] = make_float4(p10, p11, p12, p13);
        float lp0 = p00 + p01 + p02 + p03;
        float lp1 = p10 + p11 + p12 + p13;
#pragma unroll
        for (int off = 1; off < 16; off <<= 1) {
            lp0 += __shfl_xor_sync(0xffffffffu, lp0, off);
            lp1 += __shfl_xor_sync(0xffffffffu, lp1, off);
        }
        l0 = l0 * cor0 + lp0;
        l1 = l1 * cor1 + lp1;
        m0 = mn0; m1 = mn1;
#pragma unroll
        for (int j = 0; j < 4; j++) { oa0[j] *= cor0; oa1[j] *= cor1; }
        __syncthreads();

        // PV: O[2][4] += P[2][64] * V[64][4]
#pragma unroll
        for (int c = 0; c < 64; c += 4) {
            float4 pr0 = *(const float4*)&Ps[(rg*2+0)*64 + c];
            float4 pr1 = *(const float4*)&Ps[(rg*2+1)*64 + c];
#define PVSTEP(CC, PE0, PE1) { \
            float4 vv = *(const float4*)&Vs[(c+CC)*64 + cg*4]; \
            oa0[0] += PE0*vv.x; oa0[1] += PE0*vv.y; oa0[2] += PE0*vv.z; oa0[3] += PE0*vv.w; \
            oa1[0] += PE1*vv.x; oa1[1] += PE1*vv.y; oa1[2] += PE1*vv.z; oa1[3] += PE1*vv.w; }
            PVSTEP(0, pr0.x, pr1.x) PVSTEP(1, pr0.y, pr1.y)
            PVSTEP(2, pr0.z, pr1.z) PVSTEP(3, pr0.w, pr1.w)
#undef PVSTEP
        }
    }

    float il0 = 1.f / l0, il1 = 1.f / l1;
    *(float4*)&o[(size_t)(tq0 + rg*2 + 0) * E_DIM + h * 64 + cg * 4] =
        make_float4(oa0[0]*il0, oa0[1]*il0, oa0[2]*il0, oa0[3]*il0);
    *(float4*)&o[(size_t)(tq0 + rg*2 + 1) * E_DIM + h * 64 + cg * 4] =
        make_float4(oa1[0]*il1, oa1[1]*il1, oa1[2]*il1, oa1[3]*il1);
}

// -------------------------------------------------------------------
extern "C" void kernel_launch(void* const* d_in, const int* in_sizes, int n_in,
                              void* d_out, int out_size)
{
    const float* x  = (const float*)d_in[0];
    const int*   cu = (const int*)d_in[1];
    int idx = 2;
    if (in_sizes[2] == 1) idx = 3;  // skip scalar max_len if present
    const float* norm_w = (const float*)d_in[idx++];
    const float* norm_b = (const float*)d_in[idx++];
    const float* Wq     = (const float*)d_in[idx++];
    const float* Wk     = (const float*)d_in[idx++];
    const float* Wv     = (const float*)d_in[idx++];
    const float* Wout   = (const float*)d_in[idx++];
    const float* lnq_w  = (const float*)d_in[idx++];
    const float* lnk_w  = (const float*)d_in[idx++];
    float* out = (float*)d_out;

    int nb = in_sizes[1] - 1;   // 8 sequences

    float *h, *q, *k, *v, *o;
    cudaGetSymbolAddress((void**)&h, g_h);
    cudaGetSymbolAddress((void**)&q, g_q);
    cudaGetSymbolAddress((void**)&k, g_k);
    cudaGetSymbolAddress((void**)&v, g_v);
    cudaGetSymbolAddress((void**)&o, g_o);

    // 1) pre-norm
    ln_kernel<<<T_TOK, 256>>>(x, norm_w, norm_b, h);

    // 2) Q/K/V projections
    dim3 ggrid(E_DIM / 128, T_TOK / 128);
    sgemm_nt<<<ggrid, 256>>>(h, Wq, q, T_TOK, E_DIM, E_DIM);
    sgemm_nt<<<ggrid, 256>>>(h, Wk, k, T_TOK, E_DIM, E_DIM);
    sgemm_nt<<<ggrid, 256>>>(h, Wv, v, T_TOK, E_DIM, E_DIM);

    // 3) q/k LayerNorm + RoPE (in place)
    lnrope_kernel<<<T_TOK, 256>>>(q, k, lnq_w, lnk_w, cu, nb);

    // 4) attention
    dim3 agrid(SEQ / 32, NHEAD, NBATCH);
    attn_kernel<<<agrid, 256>>>(q, k, v, o);

    // 5) output projection
    sgemm_nt<<<ggrid, 256>>>(o, Wout, out, T_TOK, E_DIM, E_DIM);
}

// round 2
// speedup vs baseline: 6.0702x; 6.0702x over previous
#include <cuda_runtime.h>
#include <math.h>

#define E_DIM 1280
#define NHEAD 20
#define DHEAD 64
#define T_TOK 8192
#define SEQ   1024
#define NBATCH 8

// ---------------- scratch (no allocations allowed) ----------------
__device__ float g_h[T_TOK * E_DIM];
__device__ float g_q[T_TOK * E_DIM];
__device__ float g_k[T_TOK * E_DIM];
__device__ float g_v[T_TOK * E_DIM];
__device__ float g_o[T_TOK * E_DIM];

// ---------------- helpers ----------------
__device__ __forceinline__ unsigned f2tf(float f) {
    unsigned u;
    asm("cvt.rna.tf32.f32 %0, %1;" : "=r"(u) : "f"(f));
    return u;
}

__device__ __forceinline__ void mma_tf32(float c[4], const unsigned a[4],
                                         unsigned b0, unsigned b1) {
    asm volatile(
        "mma.sync.aligned.m16n8k8.row.col.f32.tf32.tf32.f32 "
        "{%0,%1,%2,%3}, {%4,%5,%6,%7}, {%8,%9}, {%0,%1,%2,%3};\n"
        : "+f"(c[0]), "+f"(c[1]), "+f"(c[2]), "+f"(c[3])
        : "r"(a[0]), "r"(a[1]), "r"(a[2]), "r"(a[3]), "r"(b0), "r"(b1));
}

// ---------------- LayerNorm (with bias) : x -> h -------------------
__global__ void __launch_bounds__(256) ln_kernel(
    const float* __restrict__ x, const float* __restrict__ w,
    const float* __restrict__ b, float* __restrict__ out)
{
    int t = blockIdx.x;
    const float* xr = x + (size_t)t * E_DIM;
    float vals[5];
    float s = 0.f, s2 = 0.f;
#pragma unroll
    for (int j = 0; j < 5; j++) {
        float v = xr[threadIdx.x + j * 256];
        vals[j] = v; s += v; s2 += v * v;
    }
    __shared__ float red0[8], red1[8];
    int lane = threadIdx.x & 31, wid = threadIdx.x >> 5;
#pragma unroll
    for (int o = 16; o; o >>= 1) {
        s  += __shfl_xor_sync(0xffffffffu, s,  o);
        s2 += __shfl_xor_sync(0xffffffffu, s2, o);
    }
    if (lane == 0) { red0[wid] = s; red1[wid] = s2; }
    __syncthreads();
    float ts = 0.f, ts2 = 0.f;
#pragma unroll
    for (int j = 0; j < 8; j++) { ts += red0[j]; ts2 += red1[j]; }
    float mean = ts * (1.f / E_DIM);
    float var  = ts2 * (1.f / E_DIM) - mean * mean;
    float rstd = rsqrtf(var + 1e-5f);
    float* orow = out + (size_t)t * E_DIM;
#pragma unroll
    for (int j = 0; j < 5; j++) {
        int idx = threadIdx.x + j * 256;
        orow[idx] = (vals[j] - mean) * rstd * w[idx] + b[idx];
    }
}

// ------------- LayerNorm (no bias) + RoPE, in place on q and k -----
__global__ void __launch_bounds__(256) lnrope_kernel(
    float* __restrict__ q, float* __restrict__ k,
    const float* __restrict__ wq, const float* __restrict__ wk,
    const int* __restrict__ cu, int nb)
{
    int t = blockIdx.x;
    __shared__ float sb[E_DIM];
    __shared__ float red0[8], red1[8];
    __shared__ float s_stats[2];
    int lane = threadIdx.x & 31, wid = threadIdx.x >> 5;

    int seg = 0;
    for (int bb = 1; bb < nb; bb++) if (t >= cu[bb]) seg = bb;
    float pos = (float)(t - cu[seg]);
    const float kfreq = -0.2878231366f; // -ln(10000)/32

    for (int part = 0; part < 2; part++) {
        float* base = (part ? k : q) + (size_t)t * E_DIM;
        const float* w = part ? wk : wq;
        float s = 0.f, s2 = 0.f;
        for (int i = threadIdx.x; i < E_DIM; i += 256) {
            float v = base[i];
            sb[i] = v; s += v; s2 += v * v;
        }
#pragma unroll
        for (int o = 16; o; o >>= 1) {
            s  += __shfl_xor_sync(0xffffffffu, s,  o);
            s2 += __shfl_xor_sync(0xffffffffu, s2, o);
        }
        if (lane == 0) { red0[wid] = s; red1[wid] = s2; }
        __syncthreads();
        if (threadIdx.x == 0) {
            float ts = 0.f, ts2 = 0.f;
#pragma unroll
            for (int j = 0; j < 8; j++) { ts += red0[j]; ts2 += red1[j]; }
            float mean = ts * (1.f / E_DIM);
            float var  = ts2 * (1.f / E_DIM) - mean * mean;
            s_stats[0] = mean;
            s_stats[1] = rsqrtf(var + 1e-5f);
        }
        __syncthreads();
        float mean = s_stats[0], rstd = s_stats[1];
        for (int i = threadIdx.x; i < E_DIM; i += 256) {
            int ld = i & 63;
            float xn = (sb[i] - mean) * rstd * w[i];
            int pi = (ld < 32) ? (i + 32) : (i - 32);
            float pn = (sb[pi] - mean) * rstd * w[pi];
            int fi = ld & 31;
            float ang = pos * __expf((float)fi * kfreq);
            float sn, c;
            sincosf(ang, &sn, &c);
            float rot = (ld < 32) ? -pn : pn;
            base[i] = xn * c + rot * sn;
        }
        __syncthreads();
    }
}

// ------------- tf32 tensor-core GEMM: C[m,n] = sum_k A[m,k]*B[n,k] --
// BM=128, BN=128, BK=16, 256 threads (8 warps, 4x2), warp tile 32x64.
#define AS_STRIDE 20
__global__ void __launch_bounds__(256) gemm_tf32(
    const float* __restrict__ A, const float* __restrict__ B,
    float* __restrict__ C, int M, int N, int K)
{
    __shared__ float As[128 * AS_STRIDE];
    __shared__ float Bs[128 * AS_STRIDE];
    int bm = blockIdx.y * 128, bn = blockIdx.x * 128;
    int tid = threadIdx.x, lane = tid & 31, warp = tid >> 5;
    int gid = lane >> 2, tig = lane & 3;
    int wm = (warp >> 1) * 32, wn = (warp & 1) * 64;

    float acc[2][8][4];
#pragma unroll
    for (int i = 0; i < 2; i++)
#pragma unroll
        for (int j = 0; j < 8; j++)
#pragma unroll
            for (int l = 0; l < 4; l++) acc[i][j][l] = 0.f;

    int lr = tid >> 2;           // 0..63
    int lc = (tid & 3) << 2;     // 0,4,8,12
    const float* Ap = A + (size_t)(bm + lr) * K + lc;
    const float* Bp = B + (size_t)(bn + lr) * K + lc;

    float4 ar[2], br[2];
    ar[0] = *(const float4*)(Ap);
    ar[1] = *(const float4*)(Ap + (size_t)64 * K);
    br[0] = *(const float4*)(Bp);
    br[1] = *(const float4*)(Bp + (size_t)64 * K);

#define STORE_SMEM() { \
    _Pragma("unroll") \
    for (int i = 0; i < 2; i++) { \
        int row = lr + i * 64; \
        float4 a = ar[i], bb4 = br[i]; \
        *(float4*)&As[row * AS_STRIDE + lc] = make_float4( \
            __uint_as_float(f2tf(a.x)), __uint_as_float(f2tf(a.y)), \
            __uint_as_float(f2tf(a.z)), __uint_as_float(f2tf(a.w))); \
        *(float4*)&Bs[row * AS_STRIDE + lc] = make_float4( \
            __uint_as_float(f2tf(bb4.x)), __uint_as_float(f2tf(bb4.y)), \
            __uint_as_float(f2tf(bb4.z)), __uint_as_float(f2tf(bb4.w))); \
    } }

#define COMPUTE() { \
    _Pragma("unroll") \
    for (int ks = 0; ks < 2; ks++) { \
        unsigned af[2][4]; \
        _Pragma("unroll") \
        for (int mf = 0; mf < 2; mf++) { \
            int base = (wm + mf * 16 + gid) * AS_STRIDE + ks * 8 + tig; \
            af[mf][0] = __float_as_uint(As[base]); \
            af[mf][1] = __float_as_uint(As[base + 8 * AS_STRIDE]); \
            af[mf][2] = __float_as_uint(As[base + 4]); \
            af[mf][3] = __float_as_uint(As[base + 8 * AS_STRIDE + 4]); \
        } \
        _Pragma("unroll") \
        for (int nf = 0; nf < 8; nf++) { \
            int bbase = (wn + nf * 8 + gid) * AS_STRIDE + ks * 8 + tig; \
            unsigned b0 = __float_as_uint(Bs[bbase]); \
            unsigned b1 = __float_as_uint(Bs[bbase + 4]); \
            mma_tf32(acc[0][nf], af[0], b0, b1); \
            mma_tf32(acc[1][nf], af[1], b0, b1); \
        } \
    } }

    STORE_SMEM();
    __syncthreads();

    for (int k0 = 16; k0 < K; k0 += 16) {
        ar[0] = *(const float4*)(Ap + k0);
        ar[1] = *(const float4*)(Ap + (size_t)64 * K + k0);
        br[0] = *(const float4*)(Bp + k0);
        br[1] = *(const float4*)(Bp + (size_t)64 * K + k0);
        COMPUTE();
        __syncthreads();
        STORE_SMEM();
        __syncthreads();
    }
    COMPUTE();

#pragma unroll
    for (int mf = 0; mf < 2; mf++)
#pragma unroll
        for (int nf = 0; nf < 8; nf++) {
            int row = bm + wm + mf * 16 + gid;
            int col = bn + wn + nf * 8 + 2 * tig;
            *(float2*)&C[(size_t)row * N + col] =
                make_float2(acc[mf][nf][0], acc[mf][nf][1]);
            *(float2*)&C[(size_t)(row + 8) * N + col] =
                make_float2(acc[mf][nf][2], acc[mf][nf][3]);
        }
#undef STORE_SMEM
#undef COMPUTE
}

// ------------- flash attention, tf32 tensor cores ------------------
// block: 128 threads (4 warps), 64 q rows (16/warp); kt tiles of 64 keys.
// Ps aliases Ks (written after the post-QK barrier).
#define KS_STRIDE 68
#define VS_STRIDE 72
__global__ void __launch_bounds__(128) attn_tf32(
    const float* __restrict__ q, const float* __restrict__ k,
    const float* __restrict__ v, float* __restrict__ o)
{
    __shared__ float Ks[64 * KS_STRIDE];   // also P after QK phase
    __shared__ float Vs[64 * VS_STRIDE];

    int b = blockIdx.z, h = blockIdx.y, qt = blockIdx.x;
    int tid = threadIdx.x;
    int warp = tid >> 5, lane = tid & 31;
    int gid = lane >> 2, tig = lane & 3;
    int m0 = warp * 16;
    int tq0 = b * SEQ + qt * 64;

    // Q fragments in registers, pre-scaled by D^-0.5 = 0.125 (exact pow2)
    unsigned qf[8][4];
    {
        const float* qp = q + (size_t)(tq0 + m0 + gid) * E_DIM + h * 64;
#pragma unroll
        for (int ks = 0; ks < 8; ks++) {
            int c = ks * 8 + tig;
            qf[ks][0] = f2tf(qp[c] * 0.125f);
            qf[ks][1] = f2tf(qp[(size_t)8 * E_DIM + c] * 0.125f);
            qf[ks][2] = f2tf(qp[c + 4] * 0.125f);
            qf[ks][3] = f2tf(qp[(size_t)8 * E_DIM + c + 4] * 0.125f);
        }
    }

    float mrow0 = -1e30f, mrow1 = -1e30f;
    float lrow0 = 0.f, lrow1 = 0.f;
    float oc[8][4];
#pragma unroll
    for (int i = 0; i < 8; i++)
#pragma unroll
        for (int j = 0; j < 4; j++) oc[i][j] = 0.f;

    for (int kt = 0; kt < SEQ / 64; kt++) {
        __syncthreads();   // prior PV done: Ks/Ps region free
        int tk0 = b * SEQ + kt * 64;
        for (int i = tid; i < 1024; i += 128) {
            int r = i >> 4, c4 = (i & 15) << 2;
            float4 kk = *(const float4*)&k[(size_t)(tk0 + r) * E_DIM + h * 64 + c4];
            *(float4*)&Ks[r * KS_STRIDE + c4] = make_float4(
                __uint_as_float(f2tf(kk.x)), __uint_as_float(f2tf(kk.y)),
                __uint_as_float(f2tf(kk.z)), __uint_as_float(f2tf(kk.w)));
            float4 vv = *(const float4*)&v[(size_t)(tk0 + r) * E_DIM + h * 64 + c4];
            *(float4*)&Vs[r * VS_STRIDE + c4] = make_float4(
                __uint_as_float(f2tf(vv.x)), __uint_as_float(f2tf(vv.y)),
                __uint_as_float(f2tf(vv.z)), __uint_as_float(f2tf(vv.w)));
        }
        __syncthreads();

        // ---- QK^T: S[16 x 64] per warp ----
        float sc[8][4];
#pragma unroll
        for (int i = 0; i < 8; i++)
#pragma unroll
            for (int j = 0; j < 4; j++) sc[i][j] = 0.f;
#pragma unroll
        for (int ks = 0; ks < 8; ks++) {
#pragma unroll
            for (int nf = 0; nf < 8; nf++) {
                int bb = (nf * 8 + gid) * KS_STRIDE + ks * 8 + tig;
                unsigned b0 = __float_as_uint(Ks[bb]);
                unsigned b1 = __float_as_uint(Ks[bb + 4]);
                mma_tf32(sc[nf], qf[ks], b0, b1);
            }
        }
        __syncthreads();   // all warps done reading Ks -> safe to overwrite with P

        // ---- online softmax ----
        float tm0 = -1e30f, tm1 = -1e30f;
#pragma unroll
        for (int nf = 0; nf < 8; nf++) {
            tm0 = fmaxf(tm0, fmaxf(sc[nf][0], sc[nf][1]));
            tm1 = fmaxf(tm1, fmaxf(sc[nf][2], sc[nf][3]));
        }
        tm0 = fmaxf(tm0, __shfl_xor_sync(0xffffffffu, tm0, 1));
        tm0 = fmaxf(tm0, __shfl_xor_sync(0xffffffffu, tm0, 2));
        tm1 = fmaxf(tm1, __shfl_xor_sync(0xffffffffu, tm1, 1));
        tm1 = fmaxf(tm1, __shfl_xor_sync(0xffffffffu, tm1, 2));
        float mn0 = fmaxf(mrow0, tm0), mn1 = fmaxf(mrow1, tm1);
        float cor0 = __expf(mrow0 - mn0), cor1 = __expf(mrow1 - mn1);
        float ls0 = 0.f, ls1 = 0.f;
#pragma unroll
        for (int nf = 0; nf < 8; nf++) {
            float p0 = __expf(sc[nf][0] - mn0);
            float p1 = __expf(sc[nf][1] - mn0);
            float p2 = __expf(sc[nf][2] - mn1);
            float p3 = __expf(sc[nf][3] - mn1);
            ls0 += p0 + p1; ls1 += p2 + p3;
            int pb = (m0 + gid) * KS_STRIDE + nf * 8 + 2 * tig;
            *(float2*)&Ks[pb] = make_float2(
                __uint_as_float(f2tf(p0)), __uint_as_float(f2tf(p1)));
            *(float2*)&Ks[pb + 8 * KS_STRIDE] = make_float2(
                __uint_as_float(f2tf(p2)), __uint_as_float(f2tf(p3)));
        }
        ls0 += __shfl_xor_sync(0xffffffffu, ls0, 1);
        ls0 += __shfl_xor_sync(0xffffffffu, ls0, 2);
        ls1 += __shfl_xor_sync(0xffffffffu, ls1, 1);
        ls1 += __shfl_xor_sync(0xffffffffu, ls1, 2);
        lrow0 = lrow0 * cor0 + ls0;
        lrow1 = lrow1 * cor1 + ls1;
        mrow0 = mn0; mrow1 = mn1;
#pragma unroll
        for (int nf = 0; nf < 8; nf++) {
            oc[nf][0] *= cor0; oc[nf][1] *= cor0;
            oc[nf][2] *= cor1; oc[nf][3] *= cor1;
        }
        __syncwarp();   // P writes visible to own warp (PV reads own 16 rows only)

        // ---- PV: O[16 x 64] += P[16 x 64k] * V[64k x 64] ----
#pragma unroll
        for (int ks = 0; ks < 8; ks++) {
            unsigned af[4];
            int ab = (m0 + gid) * KS_STRIDE + ks * 8 + tig;
            af[0] = __float_as_uint(Ks[ab]);
            af[1] = __float_as_uint(Ks[ab + 8 * KS_STRIDE]);
            af[2] = __float_as_uint(Ks[ab + 4]);
            af[3] = __float_as_uint(Ks[ab + 8 * KS_STRIDE + 4]);
#pragma unroll
            for (int nf = 0; nf < 8; nf++) {
                int vb = (ks * 8 + tig) * VS_STRIDE + nf * 8 + gid;
                unsigned b0 = __float_as_uint(Vs[vb]);
                unsigned b1 = __float_as_uint(Vs[vb + 4 * VS_STRIDE]);
                mma_tf32(oc[nf], af, b0, b1);
            }
        }
    }

    float il0 = 1.f / lrow0, il1 = 1.f / lrow1;
    int row = tq0 + m0 + gid;
#pragma unroll
    for (int nf = 0; nf < 8; nf++) {
        int col = h * 64 + nf * 8 + 2 * tig;
        *(float2*)&o[(size_t)row * E_DIM + col] =
            make_float2(oc[nf][0] * il0, oc[nf][1] * il0);
        *(float2*)&o[(size_t)(row + 8) * E_DIM + col] =
            make_float2(oc[nf][2] * il1, oc[nf][3] * il1);
    }
}

// -------------------------------------------------------------------
extern "C" void kernel_launch(void* const* d_in, const int* in_sizes, int n_in,
                              void* d_out, int out_size)
{
    const float* x  = (const float*)d_in[0];
    const int*   cu = (const int*)d_in[1];
    int idx = 2;
    if (in_sizes[2] == 1) idx = 3;  // skip scalar max_len if present
    const float* norm_w = (const float*)d_in[idx++];
    const float* norm_b = (const float*)d_in[idx++];
    const float* Wq     = (const float*)d_in[idx++];
    const float* Wk     = (const float*)d_in[idx++];
    const float* Wv     = (const float*)d_in[idx++];
    const float* Wout   = (const float*)d_in[idx++];
    const float* lnq_w  = (const float*)d_in[idx++];
    const float* lnk_w  = (const float*)d_in[idx++];
    float* out = (float*)d_out;

    int nb = in_sizes[1] - 1;

    float *h, *q, *k, *v, *o;
    cudaGetSymbolAddress((void**)&h, g_h);
    cudaGetSymbolAddress((void**)&q, g_q);
    cudaGetSymbolAddress((void**)&k, g_k);
    cudaGetSymbolAddress((void**)&v, g_v);
    cudaGetSymbolAddress((void**)&o, g_o);

    // 1) pre-norm
    ln_kernel<<<T_TOK, 256>>>(x, norm_w, norm_b, h);

    // 2) Q/K/V projections (tf32 tensor cores)
    dim3 ggrid(E_DIM / 128, T_TOK / 128);
    gemm_tf32<<<ggrid, 256>>>(h, Wq, q, T_TOK, E_DIM, E_DIM);
    gemm_tf32<<<ggrid, 256>>>(h, Wk, k, T_TOK, E_DIM, E_DIM);
    gemm_tf32<<<ggrid, 256>>>(h, Wv, v, T_TOK, E_DIM, E_DIM);

    // 3) q/k LayerNorm + RoPE (in place)
    lnrope_kernel<<<T_TOK, 256>>>(q, k, lnq_w, lnk_w, cu, nb);

    // 4) attention (tf32 tensor cores)
    dim3 agrid(SEQ / 64, NHEAD, NBATCH);
    attn_tf32<<<agrid, 128>>>(q, k, v, o);

    // 5) output projection
    gemm_tf32<<<ggrid, 256>>>(o, Wout, out, T_TOK, E_DIM, E_DIM);
}

// round 4
// speedup vs baseline: 6.2936x; 1.0368x over previous
#include <cuda_runtime.h>
#include <math.h>

#define E_DIM 1280
#define NHEAD 20
#define DHEAD 64
#define T_TOK 8192
#define SEQ   1024
#define NBATCH 8

// ---------------- scratch (no allocations allowed) ----------------
__device__ float g_h[T_TOK * E_DIM];
__device__ float g_q[T_TOK * E_DIM];
__device__ float g_k[T_TOK * E_DIM];
__device__ float g_v[T_TOK * E_DIM];
__device__ float g_o[T_TOK * E_DIM];
__device__ float g_cos[T_TOK * 32];
__device__ float g_sin[T_TOK * 32];

// ---------------- helpers ----------------
__device__ __forceinline__ unsigned f2tf(float f) {
    unsigned u;
    asm("cvt.rna.tf32.f32 %0, %1;" : "=r"(u) : "f"(f));
    return u;
}

__device__ __forceinline__ void mma_tf32(float c[4], const unsigned a[4],
                                         unsigned b0, unsigned b1) {
    asm volatile(
        "mma.sync.aligned.m16n8k8.row.col.f32.tf32.tf32.f32 "
        "{%0,%1,%2,%3}, {%4,%5,%6,%7}, {%8,%9}, {%0,%1,%2,%3};\n"
        : "+f"(c[0]), "+f"(c[1]), "+f"(c[2]), "+f"(c[3])
        : "r"(a[0]), "r"(a[1]), "r"(a[2]), "r"(a[3]), "r"(b0), "r"(b1));
}

__device__ __forceinline__ void cpa16(void* s, const void* g) {
    unsigned saddr = (unsigned)__cvta_generic_to_shared(s);
    asm volatile("cp.async.ca.shared.global [%0], [%1], 16;\n"
                 :: "r"(saddr), "l"(g));
}

// ---------------- LayerNorm (with bias) : x -> h -------------------
__global__ void __launch_bounds__(256) ln_kernel(
    const float* __restrict__ x, const float* __restrict__ w,
    const float* __restrict__ b, float* __restrict__ out)
{
    int t = blockIdx.x;
    const float* xr = x + (size_t)t * E_DIM;
    float vals[5];
    float s = 0.f, s2 = 0.f;
#pragma unroll
    for (int j = 0; j < 5; j++) {
        float v = xr[threadIdx.x + j * 256];
        vals[j] = v; s += v; s2 += v * v;
    }
    __shared__ float red0[8], red1[8];
    int lane = threadIdx.x & 31, wid = threadIdx.x >> 5;
#pragma unroll
    for (int o = 16; o; o >>= 1) {
        s  += __shfl_xor_sync(0xffffffffu, s,  o);
        s2 += __shfl_xor_sync(0xffffffffu, s2, o);
    }
    if (lane == 0) { red0[wid] = s; red1[wid] = s2; }
    __syncthreads();
    float ts = 0.f, ts2 = 0.f;
#pragma unroll
    for (int j = 0; j < 8; j++) { ts += red0[j]; ts2 += red1[j]; }
    float mean = ts * (1.f / E_DIM);
    float var  = ts2 * (1.f / E_DIM) - mean * mean;
    float rstd = rsqrtf(var + 1e-5f);
    float* orow = out + (size_t)t * E_DIM;
#pragma unroll
    for (int j = 0; j < 5; j++) {
        int idx = threadIdx.x + j * 256;
        orow[idx] = (vals[j] - mean) * rstd * w[idx] + b[idx];
    }
}

// ---------------- RoPE table: cos/sin per (token, freq) ------------
__global__ void __launch_bounds__(256) rope_table_kernel(
    const int* __restrict__ cu, int nb)
{
    int t = blockIdx.x * 8 + (threadIdx.x >> 5);
    int f = threadIdx.x & 31;
    int seg = 0;
    for (int bb = 1; bb < nb; bb++) if (t >= cu[bb]) seg = bb;
    float pos = (float)(t - cu[seg]);
    const float kfreq = -0.2878231366f; // -ln(10000)/32
    float ang = pos * __expf((float)f * kfreq);
    float sn, c;
    sincosf(ang, &sn, &c);
    g_cos[t * 32 + f] = c;
    g_sin[t * 32 + f] = sn;
}

// ------------- LayerNorm (no bias) + RoPE, in place ----------------
// grid (T, 2): blockIdx.y selects q (0) or k (1).
__global__ void __launch_bounds__(256) lnrope_kernel(
    float* __restrict__ q, float* __restrict__ k,
    const float* __restrict__ wq, const float* __restrict__ wk)
{
    int t = blockIdx.x;
    int part = blockIdx.y;
    __shared__ float sb[E_DIM];
    __shared__ float red0[8], red1[8];
    __shared__ float s_stats[2];
    int lane = threadIdx.x & 31, wid = threadIdx.x >> 5;

    float* base = (part ? k : q) + (size_t)t * E_DIM;
    const float* w = part ? wk : wq;
    float s = 0.f, s2 = 0.f;
    for (int i = threadIdx.x; i < E_DIM; i += 256) {
        float v = base[i];
        sb[i] = v; s += v; s2 += v * v;
    }
#pragma unroll
    for (int o = 16; o; o >>= 1) {
        s  += __shfl_xor_sync(0xffffffffu, s,  o);
        s2 += __shfl_xor_sync(0xffffffffu, s2, o);
    }
    if (lane == 0) { red0[wid] = s; red1[wid] = s2; }
    __syncthreads();
    if (threadIdx.x == 0) {
        float ts = 0.f, ts2 = 0.f;
#pragma unroll
        for (int j = 0; j < 8; j++) { ts += red0[j]; ts2 += red1[j]; }
        float mean = ts * (1.f / E_DIM);
        float var  = ts2 * (1.f / E_DIM) - mean * mean;
        s_stats[0] = mean;
        s_stats[1] = rsqrtf(var + 1e-5f);
    }
    __syncthreads();
    float mean = s_stats[0], rstd = s_stats[1];
    for (int i = threadIdx.x; i < E_DIM; i += 256) {
        int ld = i & 63;
        float xn = (sb[i] - mean) * rstd * w[i];
        int pi = (ld < 32) ? (i + 32) : (i - 32);
        float pn = (sb[pi] - mean) * rstd * w[pi];
        int fi = ld & 31;
        float c  = g_cos[t * 32 + fi];
        float sn = g_sin[t * 32 + fi];
        float rot = (ld < 32) ? -pn : pn;
        base[i] = xn * c + rot * sn;
    }
}

// ------------- tf32 GEMM core, cp.async double-buffered -------------
// BM=128, BN=128, BK=16, 256 threads (8 warps 4x2), warp tile 32x64.
#define GSTR 20
struct GemmSmem {
    float As[2][128 * GSTR];
    float Bs[2][128 * GSTR];
};

__device__ __forceinline__ void gemm_body(
    const float* __restrict__ A, const float* __restrict__ B,
    float* __restrict__ C, int bm, int bn, int N, int K, GemmSmem& sm)
{
    int tid = threadIdx.x, lane = tid & 31, warp = tid >> 5;
    int gid = lane >> 2, tig = lane & 3;
    int wm = (warp >> 1) * 32, wn = (warp & 1) * 64;

    float acc[2][8][4];
#pragma unroll
    for (int i = 0; i < 2; i++)
#pragma unroll
        for (int j = 0; j < 8; j++)
#pragma unroll
            for (int l = 0; l < 4; l++) acc[i][j][l] = 0.f;

    int lr = tid >> 2;           // 0..63
    int lc = (tid & 3) << 2;     // 0,4,8,12
    const float* Ap = A + (size_t)(bm + lr) * K + lc;
    const float* Bp = B + (size_t)(bn + lr) * K + lc;

#define ISSUE(BUF, K0) { \
    _Pragma("unroll") \
    for (int i = 0; i < 2; i++) { \
        int row = lr + i * 64; \
        cpa16(&sm.As[BUF][row * GSTR + lc], Ap + (size_t)i * 64 * K + (K0)); \
        cpa16(&sm.Bs[BUF][row * GSTR + lc], Bp + (size_t)i * 64 * K + (K0)); \
    } \
    asm volatile("cp.async.commit_group;\n"); }

#define COMPUTE(BUF) { \
    const float* Asb = sm.As[BUF]; \
    const float* Bsb = sm.Bs[BUF]; \
    _Pragma("unroll") \
    for (int ks = 0; ks < 2; ks++) { \
        unsigned af[2][4]; \
        _Pragma("unroll") \
        for (int mf = 0; mf < 2; mf++) { \
            int base = (wm + mf * 16 + gid) * GSTR + ks * 8 + tig; \
            af[mf][0] = f2tf(Asb[base]); \
            af[mf][1] = f2tf(Asb[base + 8 * GSTR]); \
            af[mf][2] = f2tf(Asb[base + 4]); \
            af[mf][3] = f2tf(Asb[base + 8 * GSTR + 4]); \
        } \
        _Pragma("unroll") \
        for (int nf = 0; nf < 8; nf++) { \
            int bb = (wn + nf * 8 + gid) * GSTR + ks * 8 + tig; \
            unsigned b0 = f2tf(Bsb[bb]); \
            unsigned b1 = f2tf(Bsb[bb + 4]); \
            mma_tf32(acc[0][nf], af[0], b0, b1); \
            mma_tf32(acc[1][nf], af[1], b0, b1); \
        } \
    } }

    ISSUE(0, 0);
    int buf = 0;
    for (int k0 = 0; k0 < K; k0 += 16) {
        if (k0 + 16 < K) {
            ISSUE(buf ^ 1, k0 + 16);
            asm volatile("cp.async.wait_group 1;\n");
        } else {
            asm volatile("cp.async.wait_group 0;\n");
        }
        __syncthreads();
        COMPUTE(buf);
        __syncthreads();
        buf ^= 1;
    }

#pragma unroll
    for (int mf = 0; mf < 2; mf++)
#pragma unroll
        for (int nf = 0; nf < 8; nf++) {
            int row = bm + wm + mf * 16 + gid;
            int col = bn + wn + nf * 8 + 2 * tig;
            *(float2*)&C[(size_t)row * N + col] =
                make_float2(acc[mf][nf][0], acc[mf][nf][1]);
            *(float2*)&C[(size_t)(row + 8) * N + col] =
                make_float2(acc[mf][nf][2], acc[mf][nf][3]);
        }
#undef ISSUE
#undef COMPUTE
}

// Merged QKV projection: grid (30, 64); 10 n-blocks per weight matrix.
__global__ void __launch_bounds__(256) gemm_qkv(
    const float* __restrict__ A,
    const float* __restrict__ Wq, const float* __restrict__ Wk,
    const float* __restrict__ Wv,
    float* __restrict__ q, float* __restrict__ k, float* __restrict__ v)
{
    __shared__ GemmSmem sm;
    int which = blockIdx.x / 10;
    int bn = (blockIdx.x % 10) * 128;
    int bm = blockIdx.y * 128;
    const float* B = (which == 0) ? Wq : (which == 1) ? Wk : Wv;
    float* C = (which == 0) ? q : (which == 1) ? k : v;
    gemm_body(A, B, C, bm, bn, E_DIM, E_DIM, sm);
}

// Single GEMM (output projection)
__global__ void __launch_bounds__(256) gemm_one(
    const float* __restrict__ A, const float* __restrict__ B,
    float* __restrict__ C)
{
    __shared__ GemmSmem sm;
    gemm_body(A, B, C, blockIdx.y * 128, blockIdx.x * 128, E_DIM, E_DIM, sm);
}

// ------------- flash attention, tf32 tensor cores ------------------
#define KS_STRIDE 68
#define VS_STRIDE 72
__global__ void __launch_bounds__(128) attn_tf32(
    const float* __restrict__ q, const float* __restrict__ k,
    const float* __restrict__ v, float* __restrict__ o)
{
    __shared__ float Ks[64 * KS_STRIDE];   // also P after QK phase
    __shared__ float Vs[64 * VS_STRIDE];

    int b = blockIdx.z, h = blockIdx.y, qt = blockIdx.x;
    int tid = threadIdx.x;
    int warp = tid >> 5, lane = tid & 31;
    int gid = lane >> 2, tig = lane & 3;
    int m0 = warp * 16;
    int tq0 = b * SEQ + qt * 64;

    unsigned qf[8][4];
    {
        const float* qp = q + (size_t)(tq0 + m0 + gid) * E_DIM + h * 64;
#pragma unroll
        for (int ks = 0; ks < 8; ks++) {
            int c = ks * 8 + tig;
            qf[ks][0] = f2tf(qp[c] * 0.125f);
            qf[ks][1] = f2tf(qp[(size_t)8 * E_DIM + c] * 0.125f);
            qf[ks][2] = f2tf(qp[c + 4] * 0.125f);
            qf[ks][3] = f2tf(qp[(size_t)8 * E_DIM + c + 4] * 0.125f);
        }
    }

    float mrow0 = -1e30f, mrow1 = -1e30f;
    float lrow0 = 0.f, lrow1 = 0.f;
    float oc[8][4];
#pragma unroll
    for (int i = 0; i < 8; i++)
#pragma unroll
        for (int j = 0; j < 4; j++) oc[i][j] = 0.f;

    for (int kt = 0; kt < SEQ / 64; kt++) {
        __syncthreads();
        int tk0 = b * SEQ + kt * 64;
        for (int i = tid; i < 1024; i += 128) {
            int r = i >> 4, c4 = (i & 15) << 2;
            float4 kk = *(const float4*)&k[(size_t)(tk0 + r) * E_DIM + h * 64 + c4];
            *(float4*)&Ks[r * KS_STRIDE + c4] = make_float4(
                __uint_as_float(f2tf(kk.x)), __uint_as_float(f2tf(kk.y)),
                __uint_as_float(f2tf(kk.z)), __uint_as_float(f2tf(kk.w)));
            float4 vv = *(const float4*)&v[(size_t)(tk0 + r) * E_DIM + h * 64 + c4];
            *(float4*)&Vs[r * VS_STRIDE + c4] = make_float4(
                __uint_as_float(f2tf(vv.x)), __uint_as_float(f2tf(vv.y)),
                __uint_as_float(f2tf(vv.z)), __uint_as_float(f2tf(vv.w)));
        }
        __syncthreads();

        float sc[8][4];
#pragma unroll
        for (int i = 0; i < 8; i++)
#pragma unroll
            for (int j = 0; j < 4; j++) sc[i][j] = 0.f;
#pragma unroll
        for (int ks = 0; ks < 8; ks++) {
#pragma unroll
            for (int nf = 0; nf < 8; nf++) {
                int bb = (nf * 8 + gid) * KS_STRIDE + ks * 8 + tig;
                unsigned b0 = __float_as_uint(Ks[bb]);
                unsigned b1 = __float_as_uint(Ks[bb + 4]);
                mma_tf32(sc[nf], qf[ks], b0, b1);
            }
        }
        __syncthreads();

        float tm0 = -1e30f, tm1 = -1e30f;
#pragma unroll
        for (int nf = 0; nf < 8; nf++) {
            tm0 = fmaxf(tm0, fmaxf(sc[nf][0], sc[nf][1]));
            tm1 = fmaxf(tm1, fmaxf(sc[nf][2], sc[nf][3]));
        }
        tm0 = fmaxf(tm0, __shfl_xor_sync(0xffffffffu, tm0, 1));
        tm0 = fmaxf(tm0, __shfl_xor_sync(0xffffffffu, tm0, 2));
        tm1 = fmaxf(tm1, __shfl_xor_sync(0xffffffffu, tm1, 1));
        tm1 = fmaxf(tm1, __shfl_xor_sync(0xffffffffu, tm1, 2));
        float mn0 = fmaxf(mrow0, tm0), mn1 = fmaxf(mrow1, tm1);
        float cor0 = __expf(mrow0 - mn0), cor1 = __expf(mrow1 - mn1);
        float ls0 = 0.f, ls1 = 0.f;
#pragma unroll
        for (int nf = 0; nf < 8; nf++) {
            float p0 = __expf(sc[nf][0] - mn0);
            float p1 = __expf(sc[nf][1] - mn0);
            float p2 = __expf(sc[nf][2] - mn1);
            float p3 = __expf(sc[nf][3] - mn1);
            ls0 += p0 + p1; ls1 += p2 + p3;
            int pb = (m0 + gid) * KS_STRIDE + nf * 8 + 2 * tig;
            *(float2*)&Ks[pb] = make_float2(
                __uint_as_float(f2tf(p0)), __uint_as_float(f2tf(p1)));
            *(float2*)&Ks[pb + 8 * KS_STRIDE] = make_float2(
                __uint_as_float(f2tf(p2)), __uint_as_float(f2tf(p3)));
        }
        ls0 += __shfl_xor_sync(0xffffffffu, ls0, 1);
        ls0 += __shfl_xor_sync(0xffffffffu, ls0, 2);
        ls1 += __shfl_xor_sync(0xffffffffu, ls1, 1);
        ls1 += __shfl_xor_sync(0xffffffffu, ls1, 2);
        lrow0 = lrow0 * cor0 + ls0;
        lrow1 = lrow1 * cor1 + ls1;
        mrow0 = mn0; mrow1 = mn1;
#pragma unroll
        for (int nf = 0; nf < 8; nf++) {
            oc[nf][0] *= cor0; oc[nf][1] *= cor0;
            oc[nf][2] *= cor1; oc[nf][3] *= cor1;
        }
        __syncwarp();

#pragma unroll
        for (int ks = 0; ks < 8; ks++) {
            unsigned af[4];
            int ab = (m0 + gid) * KS_STRIDE + ks * 8 + tig;
            af[0] = __float_as_uint(Ks[ab]);
            af[1] = __float_as_uint(Ks[ab + 8 * KS_STRIDE]);
            af[2] = __float_as_uint(Ks[ab + 4]);
            af[3] = __float_as_uint(Ks[ab + 8 * KS_STRIDE + 4]);
#pragma unroll
            for (int nf = 0; nf < 8; nf++) {
                int vb = (ks * 8 + tig) * VS_STRIDE + nf * 8 + gid;
                unsigned b0 = __float_as_uint(Vs[vb]);
                unsigned b1 = __float_as_uint(Vs[vb + 4 * VS_STRIDE]);
                mma_tf32(oc[nf], af, b0, b1);
            }
        }
    }

    float il0 = 1.f / lrow0, il1 = 1.f / lrow1;
    int row = tq0 + m0 + gid;
#pragma unroll
    for (int nf = 0; nf < 8; nf++) {
        int col = h * 64 + nf * 8 + 2 * tig;
        *(float2*)&o[(size_t)row * E_DIM + col] =
            make_float2(oc[nf][0] * il0, oc[nf][1] * il0);
        *(float2*)&o[(size_t)(row + 8) * E_DIM + col] =
            make_float2(oc[nf][2] * il1, oc[nf][3] * il1);
    }
}

// -------------------------------------------------------------------
extern "C" void kernel_launch(void* const* d_in, const int* in_sizes, int n_in,
                              void* d_out, int out_size)
{
    const float* x  = (const float*)d_in[0];
    const int*   cu = (const int*)d_in[1];
    int idx = 2;
    if (in_sizes[2] == 1) idx = 3;  // skip scalar max_len if present
    const float* norm_w = (const float*)d_in[idx++];
    const float* norm_b = (const float*)d_in[idx++];
    const float* Wq     = (const float*)d_in[idx++];
    const float* Wk     = (const float*)d_in[idx++];
    const float* Wv     = (const float*)d_in[idx++];
    const float* Wout   = (const float*)d_in[idx++];
    const float* lnq_w  = (const float*)d_in[idx++];
    const float* lnk_w  = (const float*)d_in[idx++];
    float* out = (float*)d_out;

    int nb = in_sizes[1] - 1;

    float *h, *q, *k, *v, *o;
    cudaGetSymbolAddress((void**)&h, g_h);
    cudaGetSymbolAddress((void**)&q, g_q);
    cudaGetSymbolAddress((void**)&k, g_k);
    cudaGetSymbolAddress((void**)&v, g_v);
    cudaGetSymbolAddress((void**)&o, g_o);

    // 1) pre-norm + rope table (independent)
    ln_kernel<<<T_TOK, 256>>>(x, norm_w, norm_b, h);
    rope_table_kernel<<<T_TOK / 8, 256>>>(cu, nb);

    // 2) merged Q/K/V projections (tf32 + cp.async pipeline)
    gemm_qkv<<<dim3(30, T_TOK / 128), 256>>>(h, Wq, Wk, Wv, q, k, v);

    // 3) q/k LayerNorm + RoPE (in place, parallel over q/k)
    lnrope_kernel<<<dim3(T_TOK, 2), 256>>>(q, k, lnq_w, lnk_w);

    // 4) attention
    dim3 agrid(SEQ / 64, NHEAD, NBATCH);
    attn_tf32<<<agrid, 128>>>(q, k, v, o);

    // 5) output projection
    gemm_one<<<dim3(E_DIM / 128, T_TOK / 128), 256>>>(o, Wout, out);
}

// round 5
// speedup vs baseline: 6.3398x; 1.0074x over previous
#include <cuda_runtime.h>
#include <math.h>

#define E_DIM 1280
#define NHEAD 20
#define DHEAD 64
#define T_TOK 8192
#define SEQ   1024
#define NBATCH 8

// ---------------- scratch (no allocations allowed) ----------------
__device__ float g_h[T_TOK * E_DIM];
__device__ float g_q[T_TOK * E_DIM];
__device__ float g_k[T_TOK * E_DIM];
__device__ float g_v[T_TOK * E_DIM];
__device__ float g_o[T_TOK * E_DIM];
__device__ float g_wq[E_DIM * E_DIM];
__device__ float g_wk[E_DIM * E_DIM];
__device__ float g_wv[E_DIM * E_DIM];
__device__ float g_wo[E_DIM * E_DIM];
__device__ float g_cos[T_TOK * 32];
__device__ float g_sin[T_TOK * 32];

// ---------------- helpers ----------------
__device__ __forceinline__ unsigned f2tf(float f) {
    unsigned u;
    asm("cvt.rna.tf32.f32 %0, %1;" : "=r"(u) : "f"(f));
    return u;
}
__device__ __forceinline__ float f2tff(float f) {
    return __uint_as_float(f2tf(f));
}

__device__ __forceinline__ void mma_tf32(float c[4], const unsigned a[4],
                                         unsigned b0, unsigned b1) {
    asm volatile(
        "mma.sync.aligned.m16n8k8.row.col.f32.tf32.tf32.f32 "
        "{%0,%1,%2,%3}, {%4,%5,%6,%7}, {%8,%9}, {%0,%1,%2,%3};\n"
        : "+f"(c[0]), "+f"(c[1]), "+f"(c[2]), "+f"(c[3])
        : "r"(a[0]), "r"(a[1]), "r"(a[2]), "r"(a[3]), "r"(b0), "r"(b1));
}

__device__ __forceinline__ void cpa16(void* s, const void* g) {
    unsigned saddr = (unsigned)__cvta_generic_to_shared(s);
    asm volatile("cp.async.ca.shared.global [%0], [%1], 16;\n"
                 :: "r"(saddr), "l"(g));
}

// ------------- weight prep: round to tf32 in global ---------------
// grid (E*E/16/256, 4); each thread handles one float4.
__global__ void __launch_bounds__(256) wprep_kernel(
    const float* __restrict__ Wq, const float* __restrict__ Wk,
    const float* __restrict__ Wv, const float* __restrict__ Wo)
{
    const float* src = (blockIdx.y == 0) ? Wq : (blockIdx.y == 1) ? Wk :
                       (blockIdx.y == 2) ? Wv : Wo;
    float* dst = (blockIdx.y == 0) ? g_wq : (blockIdx.y == 1) ? g_wk :
                 (blockIdx.y == 2) ? g_wv : g_wo;
    int i = (blockIdx.x * 256 + threadIdx.x) * 4;
    float4 v = *(const float4*)&src[i];
    *(float4*)&dst[i] = make_float4(f2tff(v.x), f2tff(v.y), f2tff(v.z), f2tff(v.w));
}

// ---------------- LayerNorm (with bias) : x -> h (tf32-rounded) ----
__global__ void __launch_bounds__(256) ln_kernel(
    const float* __restrict__ x, const float* __restrict__ w,
    const float* __restrict__ b, float* __restrict__ out)
{
    int t = blockIdx.x;
    const float* xr = x + (size_t)t * E_DIM;
    float vals[5];
    float s = 0.f, s2 = 0.f;
#pragma unroll
    for (int j = 0; j < 5; j++) {
        float v = xr[threadIdx.x + j * 256];
        vals[j] = v; s += v; s2 += v * v;
    }
    __shared__ float red0[8], red1[8];
    int lane = threadIdx.x & 31, wid = threadIdx.x >> 5;
#pragma unroll
    for (int o = 16; o; o >>= 1) {
        s  += __shfl_xor_sync(0xffffffffu, s,  o);
        s2 += __shfl_xor_sync(0xffffffffu, s2, o);
    }
    if (lane == 0) { red0[wid] = s; red1[wid] = s2; }
    __syncthreads();
    float ts = 0.f, ts2 = 0.f;
#pragma unroll
    for (int j = 0; j < 8; j++) { ts += red0[j]; ts2 += red1[j]; }
    float mean = ts * (1.f / E_DIM);
    float var  = ts2 * (1.f / E_DIM) - mean * mean;
    float rstd = rsqrtf(var + 1e-5f);
    float* orow = out + (size_t)t * E_DIM;
#pragma unroll
    for (int j = 0; j < 5; j++) {
        int idx = threadIdx.x + j * 256;
        orow[idx] = f2tff((vals[j] - mean) * rstd * w[idx] + b[idx]);
    }
}

// ---------------- RoPE table: cos/sin per (token, freq) ------------
__global__ void __launch_bounds__(256) rope_table_kernel(
    const int* __restrict__ cu, int nb)
{
    int t = blockIdx.x * 8 + (threadIdx.x >> 5);
    int f = threadIdx.x & 31;
    int seg = 0;
    for (int bb = 1; bb < nb; bb++) if (t >= cu[bb]) seg = bb;
    float pos = (float)(t - cu[seg]);
    const float kfreq = -0.2878231366f; // -ln(10000)/32
    float ang = pos * __expf((float)f * kfreq);
    float sn, c;
    sincosf(ang, &sn, &c);
    g_cos[t * 32 + f] = c;
    g_sin[t * 32 + f] = sn;
}

// ------------- LayerNorm (no bias) + RoPE, in place (rounded) ------
// grid (T, 2): blockIdx.y selects q (0) or k (1).
__global__ void __launch_bounds__(256) lnrope_kernel(
    float* __restrict__ q, float* __restrict__ k,
    const float* __restrict__ wq, const float* __restrict__ wk)
{
    int t = blockIdx.x;
    int part = blockIdx.y;
    __shared__ float sb[E_DIM];
    __shared__ float red0[8], red1[8];
    __shared__ float s_stats[2];
    int lane = threadIdx.x & 31, wid = threadIdx.x >> 5;

    float* base = (part ? k : q) + (size_t)t * E_DIM;
    const float* w = part ? wk : wq;
    float s = 0.f, s2 = 0.f;
    for (int i = threadIdx.x; i < E_DIM; i += 256) {
        float v = base[i];
        sb[i] = v; s += v; s2 += v * v;
    }
#pragma unroll
    for (int o = 16; o; o >>= 1) {
        s  += __shfl_xor_sync(0xffffffffu, s,  o);
        s2 += __shfl_xor_sync(0xffffffffu, s2, o);
    }
    if (lane == 0) { red0[wid] = s; red1[wid] = s2; }
    __syncthreads();
    if (threadIdx.x == 0) {
        float ts = 0.f, ts2 = 0.f;
#pragma unroll
        for (int j = 0; j < 8; j++) { ts += red0[j]; ts2 += red1[j]; }
        float mean = ts * (1.f / E_DIM);
        float var  = ts2 * (1.f / E_DIM) - mean * mean;
        s_stats[0] = mean;
        s_stats[1] = rsqrtf(var + 1e-5f);
    }
    __syncthreads();
    float mean = s_stats[0], rstd = s_stats[1];
    for (int i = threadIdx.x; i < E_DIM; i += 256) {
        int ld = i & 63;
        float xn = (sb[i] - mean) * rstd * w[i];
        int pi = (ld < 32) ? (i + 32) : (i - 32);
        float pn = (sb[pi] - mean) * rstd * w[pi];
        int fi = ld & 31;
        float c  = g_cos[t * 32 + fi];
        float sn = g_sin[t * 32 + fi];
        float rot = (ld < 32) ? -pn : pn;
        base[i] = f2tff(xn * c + rot * sn);
    }
}

// ------------- tf32 GEMM core, cp.async double-buffered -------------
// Operands are PRE-ROUNDED to tf32 in global memory: no cvt in loop.
// BM=128, BN=128, BK=16, 256 threads (8 warps 4x2), warp tile 32x64.
#define GSTR 20
struct GemmSmem {
    float As[2][128 * GSTR];
    float Bs[2][128 * GSTR];
};

__device__ __forceinline__ void gemm_body(
    const float* __restrict__ A, const float* __restrict__ B,
    float* __restrict__ C, int bm, int bn, int N, int K, GemmSmem& sm)
{
    int tid = threadIdx.x, lane = tid & 31, warp = tid >> 5;
    int gid = lane >> 2, tig = lane & 3;
    int wm = (warp >> 1) * 32, wn = (warp & 1) * 64;

    float acc[2][8][4];
#pragma unroll
    for (int i = 0; i < 2; i++)
#pragma unroll
        for (int j = 0; j < 8; j++)
#pragma unroll
            for (int l = 0; l < 4; l++) acc[i][j][l] = 0.f;

    int lr = tid >> 2;           // 0..63
    int lc = (tid & 3) << 2;     // 0,4,8,12
    const float* Ap = A + (size_t)(bm + lr) * K + lc;
    const float* Bp = B + (size_t)(bn + lr) * K + lc;

#define ISSUE(BUF, K0) { \
    _Pragma("unroll") \
    for (int i = 0; i < 2; i++) { \
        int row = lr + i * 64; \
        cpa16(&sm.As[BUF][row * GSTR + lc], Ap + (size_t)i * 64 * K + (K0)); \
        cpa16(&sm.Bs[BUF][row * GSTR + lc], Bp + (size_t)i * 64 * K + (K0)); \
    } \
    asm volatile("cp.async.commit_group;\n"); }

#define COMPUTE(BUF) { \
    const float* Asb = sm.As[BUF]; \
    const float* Bsb = sm.Bs[BUF]; \
    _Pragma("unroll") \
    for (int ks = 0; ks < 2; ks++) { \
        unsigned af[2][4]; \
        _Pragma("unroll") \
        for (int mf = 0; mf < 2; mf++) { \
            int base = (wm + mf * 16 + gid) * GSTR + ks * 8 + tig; \
            af[mf][0] = __float_as_uint(Asb[base]); \
            af[mf][1] = __float_as_uint(Asb[base + 8 * GSTR]); \
            af[mf][2] = __float_as_uint(Asb[base + 4]); \
            af[mf][3] = __float_as_uint(Asb[base + 8 * GSTR + 4]); \
        } \
        _Pragma("unroll") \
        for (int nf = 0; nf < 8; nf++) { \
            int bb = (wn + nf * 8 + gid) * GSTR + ks * 8 + tig; \
            unsigned b0 = __float_as_uint(Bsb[bb]); \
            unsigned b1 = __float_as_uint(Bsb[bb + 4]); \
            mma_tf32(acc[0][nf], af[0], b0, b1); \
            mma_tf32(acc[1][nf], af[1], b0, b1); \
        } \
    } }

    ISSUE(0, 0);
    int buf = 0;
    for (int k0 = 0; k0 < K; k0 += 16) {
        if (k0 + 16 < K) {
            ISSUE(buf ^ 1, k0 + 16);
            asm volatile("cp.async.wait_group 1;\n");
        } else {
            asm volatile("cp.async.wait_group 0;\n");
        }
        __syncthreads();
        COMPUTE(buf);
        __syncthreads();
        buf ^= 1;
    }

#pragma unroll
    for (int mf = 0; mf < 2; mf++)
#pragma unroll
        for (int nf = 0; nf < 8; nf++) {
            int row = bm + wm + mf * 16 + gid;
            int col = bn + wn + nf * 8 + 2 * tig;
            *(float2*)&C[(size_t)row * N + col] =
                make_float2(acc[mf][nf][0], acc[mf][nf][1]);
            *(float2*)&C[(size_t)(row + 8) * N + col] =
                make_float2(acc[mf][nf][2], acc[mf][nf][3]);
        }
#undef ISSUE
#undef COMPUTE
}

// Merged QKV projection: grid (30, 64); 10 n-blocks per weight matrix.
__global__ void __launch_bounds__(256) gemm_qkv(
    const float* __restrict__ A,
    float* __restrict__ q, float* __restrict__ k, float* __restrict__ v)
{
    __shared__ GemmSmem sm;
    int which = blockIdx.x / 10;
    int bn = (blockIdx.x % 10) * 128;
    int bm = blockIdx.y * 128;
    const float* B = (which == 0) ? g_wq : (which == 1) ? g_wk : g_wv;
    float* C = (which == 0) ? q : (which == 1) ? k : v;
    gemm_body(A, B, C, bm, bn, E_DIM, E_DIM, sm);
}

// Single GEMM (output projection), B = g_wo
__global__ void __launch_bounds__(256) gemm_one(
    const float* __restrict__ A, float* __restrict__ C)
{
    __shared__ GemmSmem sm;
    gemm_body(A, g_wo, C, blockIdx.y * 128, blockIdx.x * 128, E_DIM, E_DIM, sm);
}

// ------------- flash attention, tf32 tensor cores ------------------
#define KS_STRIDE 68
#define VS_STRIDE 72
__global__ void __launch_bounds__(128) attn_tf32(
    const float* __restrict__ q, const float* __restrict__ k,
    const float* __restrict__ v, float* __restrict__ o)
{
    __shared__ float Ks[64 * KS_STRIDE];   // also P after QK phase
    __shared__ float Vs[64 * VS_STRIDE];

    int b = blockIdx.z, h = blockIdx.y, qt = blockIdx.x;
    int tid = threadIdx.x;
    int warp = tid >> 5, lane = tid & 31;
    int gid = lane >> 2, tig = lane & 3;
    int m0 = warp * 16;
    int tq0 = b * SEQ + qt * 64;

    unsigned qf[8][4];
    {
        const float* qp = q + (size_t)(tq0 + m0 + gid) * E_DIM + h * 64;
#pragma unroll
        for (int ks = 0; ks < 8; ks++) {
            int c = ks * 8 + tig;
            qf[ks][0] = f2tf(qp[c] * 0.125f);
            qf[ks][1] = f2tf(qp[(size_t)8 * E_DIM + c] * 0.125f);
            qf[ks][2] = f2tf(qp[c + 4] * 0.125f);
            qf[ks][3] = f2tf(qp[(size_t)8 * E_DIM + c + 4] * 0.125f);
        }
    }

    float mrow0 = -1e30f, mrow1 = -1e30f;
    float lrow0 = 0.f, lrow1 = 0.f;
    float oc[8][4];
#pragma unroll
    for (int i = 0; i < 8; i++)
#pragma unroll
        for (int j = 0; j < 4; j++) oc[i][j] = 0.f;

    for (int kt = 0; kt < SEQ / 64; kt++) {
        __syncthreads();
        int tk0 = b * SEQ + kt * 64;
        for (int i = tid; i < 1024; i += 128) {
            int r = i >> 4, c4 = (i & 15) << 2;
            float4 kk = *(const float4*)&k[(size_t)(tk0 + r) * E_DIM + h * 64 + c4];
            *(float4*)&Ks[r * KS_STRIDE + c4] = make_float4(
                f2tff(kk.x), f2tff(kk.y), f2tff(kk.z), f2tff(kk.w));
            float4 vv = *(const float4*)&v[(size_t)(tk0 + r) * E_DIM + h * 64 + c4];
            *(float4*)&Vs[r * VS_STRIDE + c4] = make_float4(
                f2tff(vv.x), f2tff(vv.y), f2tff(vv.z), f2tff(vv.w));
        }
        __syncthreads();

        float sc[8][4];
#pragma unroll
        for (int i = 0; i < 8; i++)
#pragma unroll
            for (int j = 0; j < 4; j++) sc[i][j] = 0.f;
#pragma unroll
        for (int ks = 0; ks < 8; ks++) {
#pragma unroll
            for (int nf = 0; nf < 8; nf++) {
                int bb = (nf * 8 + gid) * KS_STRIDE + ks * 8 + tig;
                unsigned b0 = __float_as_uint(Ks[bb]);
                unsigned b1 = __float_as_uint(Ks[bb + 4]);
                mma_tf32(sc[nf], qf[ks], b0, b1);
            }
        }
        __syncthreads();

        float tm0 = -1e30f, tm1 = -1e30f;
#pragma unroll
        for (int nf = 0; nf < 8; nf++) {
            tm0 = fmaxf(tm0, fmaxf(sc[nf][0], sc[nf][1]));
            tm1 = fmaxf(tm1, fmaxf(sc[nf][2], sc[nf][3]));
        }
        tm0 = fmaxf(tm0, __shfl_xor_sync(0xffffffffu, tm0, 1));
        tm0 = fmaxf(tm0, __shfl_xor_sync(0xffffffffu, tm0, 2));
        tm1 = fmaxf(tm1, __shfl_xor_sync(0xffffffffu, tm1, 1));
        tm1 = fmaxf(tm1, __shfl_xor_sync(0xffffffffu, tm1, 2));
        float mn0 = fmaxf(mrow0, tm0), mn1 = fmaxf(mrow1, tm1);
        float cor0 = __expf(mrow0 - mn0), cor1 = __expf(mrow1 - mn1);
        float ls0 = 0.f, ls1 = 0.f;
#pragma unroll
        for (int nf = 0; nf < 8; nf++) {
            float p0 = __expf(sc[nf][0] - mn0);
            float p1 = __expf(sc[nf][1] - mn0);
            float p2 = __expf(sc[nf][2] - mn1);
            float p3 = __expf(sc[nf][3] - mn1);
            ls0 += p0 + p1; ls1 += p2 + p3;
            int pb = (m0 + gid) * KS_STRIDE + nf * 8 + 2 * tig;
            *(float2*)&Ks[pb] = make_float2(f2tff(p0), f2tff(p1));
            *(float2*)&Ks[pb + 8 * KS_STRIDE] = make_float2(f2tff(p2), f2tff(p3));
        }
        ls0 += __shfl_xor_sync(0xffffffffu, ls0, 1);
        ls0 += __shfl_xor_sync(0xffffffffu, ls0, 2);
        ls1 += __shfl_xor_sync(0xffffffffu, ls1, 1);
        ls1 += __shfl_xor_sync(0xffffffffu, ls1, 2);
        lrow0 = lrow0 * cor0 + ls0;
        lrow1 = lrow1 * cor1 + ls1;
        mrow0 = mn0; mrow1 = mn1;
#pragma unroll
        for (int nf = 0; nf < 8; nf++) {
            oc[nf][0] *= cor0; oc[nf][1] *= cor0;
            oc[nf][2] *= cor1; oc[nf][3] *= cor1;
        }
        __syncwarp();

#pragma unroll
        for (int ks = 0; ks < 8; ks++) {
            unsigned af[4];
            int ab = (m0 + gid) * KS_STRIDE + ks * 8 + tig;
            af[0] = __float_as_uint(Ks[ab]);
            af[1] = __float_as_uint(Ks[ab + 8 * KS_STRIDE]);
            af[2] = __float_as_uint(Ks[ab + 4]);
            af[3] = __float_as_uint(Ks[ab + 8 * KS_STRIDE + 4]);
#pragma unroll
            for (int nf = 0; nf < 8; nf++) {
                int vb = (ks * 8 + tig) * VS_STRIDE + nf * 8 + gid;
                unsigned b0 = __float_as_uint(Vs[vb]);
                unsigned b1 = __float_as_uint(Vs[vb + 4 * VS_STRIDE]);
                mma_tf32(oc[nf], af, b0, b1);
            }
        }
    }

    // write o rounded to tf32 -> Wout GEMM needs no in-loop cvt
    float il0 = 1.f / lrow0, il1 = 1.f / lrow1;
    int row = tq0 + m0 + gid;
#pragma unroll
    for (int nf = 0; nf < 8; nf++) {
        int col = h * 64 + nf * 8 + 2 * tig;
        *(float2*)&o[(size_t)row * E_DIM + col] =
            make_float2(f2tff(oc[nf][0] * il0), f2tff(oc[nf][1] * il0));
        *(float2*)&o[(size_t)(row + 8) * E_DIM + col] =
            make_float2(f2tff(oc[nf][2] * il1), f2tff(oc[nf][3] * il1));
    }
}

// -------------------------------------------------------------------
extern "C" void kernel_launch(void* const* d_in, const int* in_sizes, int n_in,
                              void* d_out, int out_size)
{
    const float* x  = (const float*)d_in[0];
    const int*   cu = (const int*)d_in[1];
    int idx = 2;
    if (in_sizes[2] == 1) idx = 3;  // skip scalar max_len if present
    const float* norm_w = (const float*)d_in[idx++];
    const float* norm_b = (const float*)d_in[idx++];
    const float* Wq     = (const float*)d_in[idx++];
    const float* Wk     = (const float*)d_in[idx++];
    const float* Wv     = (const float*)d_in[idx++];
    const float* Wout   = (const float*)d_in[idx++];
    const float* lnq_w  = (const float*)d_in[idx++];
    const float* lnk_w  = (const float*)d_in[idx++];
    float* out = (float*)d_out;

    int nb = in_sizes[1] - 1;

    float *h, *q, *k, *v, *o;
    cudaGetSymbolAddress((void**)&h, g_h);
    cudaGetSymbolAddress((void**)&q, g_q);
    cudaGetSymbolAddress((void**)&k, g_k);
    cudaGetSymbolAddress((void**)&v, g_v);
    cudaGetSymbolAddress((void**)&o, g_o);

    // 0) round weights to tf32 once per call (~10us, 4x6.5MB)
    wprep_kernel<<<dim3(E_DIM * E_DIM / 1024, 4), 256>>>(Wq, Wk, Wv, Wout);

    // 1) pre-norm (tf32-rounded output) + rope table
    ln_kernel<<<T_TOK, 256>>>(x, norm_w, norm_b, h);
    rope_table_kernel<<<T_TOK / 8, 256>>>(cu, nb);

    // 2) merged Q/K/V projections (cvt-free cp.async mainloop)
    gemm_qkv<<<dim3(30, T_TOK / 128), 256>>>(h, q, k, v);

    // 3) q/k LayerNorm + RoPE (in place, rounded output)
    lnrope_kernel<<<dim3(T_TOK, 2), 256>>>(q, k, lnq_w, lnk_w);

    // 4) attention (rounded o output)
    dim3 agrid(SEQ / 64, NHEAD, NBATCH);
    attn_tf32<<<agrid, 128>>>(q, k, v, o);

    // 5) output projection
    gemm_one<<<dim3(E_DIM / 128, T_TOK / 128), 256>>>(o, out);
}

// round 7
// speedup vs baseline: 6.7065x; 1.0578x over previous
#include <cuda_runtime.h>
#include <math.h>

#define E_DIM 1280
#define NHEAD 20
#define DHEAD 64
#define T_TOK 8192
#define SEQ   1024
#define NBATCH 8

// ---------------- scratch (no allocations allowed) ----------------
__device__ float g_h[T_TOK * E_DIM];
__device__ float g_q[T_TOK * E_DIM];
__device__ float g_k[T_TOK * E_DIM];
__device__ float g_v[T_TOK * E_DIM];
__device__ float g_o[T_TOK * E_DIM];
__device__ float g_wq[E_DIM * E_DIM];
__device__ float g_wk[E_DIM * E_DIM];
__device__ float g_wv[E_DIM * E_DIM];
__device__ float g_wo[E_DIM * E_DIM];
__device__ float g_cos[T_TOK * 32];
__device__ float g_sin[T_TOK * 32];

// ---------------- helpers ----------------
__device__ __forceinline__ unsigned f2tf(float f) {
    unsigned u;
    asm("cvt.rna.tf32.f32 %0, %1;" : "=r"(u) : "f"(f));
    return u;
}
__device__ __forceinline__ float f2tff(float f) {
    return __uint_as_float(f2tf(f));
}

__device__ __forceinline__ void mma_tf32(float c[4], const unsigned a[4],
                                         unsigned b0, unsigned b1) {
    asm volatile(
        "mma.sync.aligned.m16n8k8.row.col.f32.tf32.tf32.f32 "
        "{%0,%1,%2,%3}, {%4,%5,%6,%7}, {%8,%9}, {%0,%1,%2,%3};\n"
        : "+f"(c[0]), "+f"(c[1]), "+f"(c[2]), "+f"(c[3])
        : "r"(a[0]), "r"(a[1]), "r"(a[2]), "r"(a[3]), "r"(b0), "r"(b1));
}

__device__ __forceinline__ void cpa16(void* s, const void* g) {
    unsigned saddr = (unsigned)__cvta_generic_to_shared(s);
    asm volatile("cp.async.ca.shared.global [%0], [%1], 16;\n"
                 :: "r"(saddr), "l"(g));
}
#define CP_COMMIT() asm volatile("cp.async.commit_group;\n" ::: "memory")
#define CP_WAIT(N)  asm volatile("cp.async.wait_group " #N ";\n" ::: "memory")

// ------------- weight prep: round to tf32 in global ---------------
__global__ void __launch_bounds__(256) wprep_kernel(
    const float* __restrict__ Wq, const float* __restrict__ Wk,
    const float* __restrict__ Wv, const float* __restrict__ Wo)
{
    const float* src = (blockIdx.y == 0) ? Wq : (blockIdx.y == 1) ? Wk :
                       (blockIdx.y == 2) ? Wv : Wo;
    float* dst = (blockIdx.y == 0) ? g_wq : (blockIdx.y == 1) ? g_wk :
                 (blockIdx.y == 2) ? g_wv : g_wo;
    int i = (blockIdx.x * 256 + threadIdx.x) * 4;
    float4 v = *(const float4*)&src[i];
    *(float4*)&dst[i] = make_float4(f2tff(v.x), f2tff(v.y), f2tff(v.z), f2tff(v.w));
}

// ---------------- LayerNorm (with bias) : x -> h (tf32-rounded) ----
__global__ void __launch_bounds__(256) ln_kernel(
    const float* __restrict__ x, const float* __restrict__ w,
    const float* __restrict__ b, float* __restrict__ out)
{
    int t = blockIdx.x;
    const float* xr = x + (size_t)t * E_DIM;
    float vals[5];
    float s = 0.f, s2 = 0.f;
#pragma unroll
    for (int j = 0; j < 5; j++) {
        float v = xr[threadIdx.x + j * 256];
        vals[j] = v; s += v; s2 += v * v;
    }
    __shared__ float red0[8], red1[8];
    int lane = threadIdx.x & 31, wid = threadIdx.x >> 5;
#pragma unroll
    for (int o = 16; o; o >>= 1) {
        s  += __shfl_xor_sync(0xffffffffu, s,  o);
        s2 += __shfl_xor_sync(0xffffffffu, s2, o);
    }
    if (lane == 0) { red0[wid] = s; red1[wid] = s2; }
    __syncthreads();
    float ts = 0.f, ts2 = 0.f;
#pragma unroll
    for (int j = 0; j < 8; j++) { ts += red0[j]; ts2 += red1[j]; }
    float mean = ts * (1.f / E_DIM);
    float var  = ts2 * (1.f / E_DIM) - mean * mean;
    float rstd = rsqrtf(var + 1e-5f);
    float* orow = out + (size_t)t * E_DIM;
#pragma unroll
    for (int j = 0; j < 5; j++) {
        int idx = threadIdx.x + j * 256;
        orow[idx] = f2tff((vals[j] - mean) * rstd * w[idx] + b[idx]);
    }
}

// ---------------- RoPE table: cos/sin per (token, freq) ------------
__global__ void __launch_bounds__(256) rope_table_kernel(
    const int* __restrict__ cu, int nb)
{
    int t = blockIdx.x * 8 + (threadIdx.x >> 5);
    int f = threadIdx.x & 31;
    int seg = 0;
    for (int bb = 1; bb < nb; bb++) if (t >= cu[bb]) seg = bb;
    float pos = (float)(t - cu[seg]);
    const float kfreq = -0.2878231366f; // -ln(10000)/32
    float ang = pos * __expf((float)f * kfreq);
    float sn, c;
    sincosf(ang, &sn, &c);
    g_cos[t * 32 + f] = c;
    g_sin[t * 32 + f] = sn;
}

// ------------- LayerNorm (no bias) + RoPE, in place (rounded) ------
__global__ void __launch_bounds__(256) lnrope_kernel(
    float* __restrict__ q, float* __restrict__ k,
    const float* __restrict__ wq, const float* __restrict__ wk)
{
    int t = blockIdx.x;
    int part = blockIdx.y;
    __shared__ float sb[E_DIM];
    __shared__ float red0[8], red1[8];
    __shared__ float s_stats[2];
    int lane = threadIdx.x & 31, wid = threadIdx.x >> 5;

    float* base = (part ? k : q) + (size_t)t * E_DIM;
    const float* w = part ? wk : wq;
    float s = 0.f, s2 = 0.f;
    for (int i = threadIdx.x; i < E_DIM; i += 256) {
        float v = base[i];
        sb[i] = v; s += v; s2 += v * v;
    }
#pragma unroll
    for (int o = 16; o; o >>= 1) {
        s  += __shfl_xor_sync(0xffffffffu, s,  o);
        s2 += __shfl_xor_sync(0xffffffffu, s2, o);
    }
    if (lane == 0) { red0[wid] = s; red1[wid] = s2; }
    __syncthreads();
    if (threadIdx.x == 0) {
        float ts = 0.f, ts2 = 0.f;
#pragma unroll
        for (int j = 0; j < 8; j++) { ts += red0[j]; ts2 += red1[j]; }
        float mean = ts * (1.f / E_DIM);
        float var  = ts2 * (1.f / E_DIM) - mean * mean;
        s_stats[0] = mean;
        s_stats[1] = rsqrtf(var + 1e-5f);
    }
    __syncthreads();
    float mean = s_stats[0], rstd = s_stats[1];
    for (int i = threadIdx.x; i < E_DIM; i += 256) {
        int ld = i & 63;
        float xn = (sb[i] - mean) * rstd * w[i];
        int pi = (ld < 32) ? (i + 32) : (i - 32);
        float pn = (sb[pi] - mean) * rstd * w[pi];
        int fi = ld & 31;
        float c  = g_cos[t * 32 + fi];
        float sn = g_sin[t * 32 + fi];
        float rot = (ld < 32) ? -pn : pn;
        base[i] = f2tff(xn * c + rot * sn);
    }
}

// ------------- tf32 GEMM core, 4-stage cp.async pipeline -----------
// Operands PRE-ROUNDED to tf32 in global. One __syncthreads per k-tile.
// BM=128, BN=128, BK=16, 256 threads (8 warps 4x2), warp tile 32x64.
// NOTE: macro-internal loop var is `ii` -- macro ARGUMENTS may contain `i`
// (the mainloop variable); an inner `i` would capture it (R6 bug).
#define GSTR 20
#define GSTAGE_F (2 * 128 * GSTR)            // floats per stage (A then B)
#define GEMM_SMEM_BYTES (4 * GSTAGE_F * 4)   // 81920

__device__ __forceinline__ void gemm_body(
    const float* __restrict__ A, const float* __restrict__ B,
    float* __restrict__ C, int bm, int bn, int N, int K,
    float* sd, bool rnd)
{
    int tid = threadIdx.x, lane = tid & 31, warp = tid >> 5;
    int gid = lane >> 2, tig = lane & 3;
    int wm = (warp >> 1) * 32, wn = (warp & 1) * 64;

    float acc[2][8][4];
#pragma unroll
    for (int i = 0; i < 2; i++)
#pragma unroll
        for (int j = 0; j < 8; j++)
#pragma unroll
            for (int l = 0; l < 4; l++) acc[i][j][l] = 0.f;

    int lr = tid >> 2;           // 0..63
    int lc = (tid & 3) << 2;     // 0,4,8,12
    const float* Ap = A + (size_t)(bm + lr) * K + lc;
    const float* Bp = B + (size_t)(bn + lr) * K + lc;

#define ISSUE(S, K0) { \
    int s_ = (S); int k0_ = (K0); \
    float* As_ = sd + s_ * GSTAGE_F; \
    float* Bs_ = As_ + 128 * GSTR; \
    _Pragma("unroll") \
    for (int ii = 0; ii < 2; ii++) { \
        int row = lr + ii * 64; \
        cpa16(&As_[row * GSTR + lc], Ap + (size_t)ii * 64 * K + k0_); \
        cpa16(&Bs_[row * GSTR + lc], Bp + (size_t)ii * 64 * K + k0_); \
    } }

#define COMPUTE(S) { \
    const float* Asb = sd + (S) * GSTAGE_F; \
    const float* Bsb = Asb + 128 * GSTR; \
    _Pragma("unroll") \
    for (int ks = 0; ks < 2; ks++) { \
        unsigned af[2][4]; \
        _Pragma("unroll") \
        for (int mf = 0; mf < 2; mf++) { \
            int base = (wm + mf * 16 + gid) * GSTR + ks * 8 + tig; \
            af[mf][0] = __float_as_uint(Asb[base]); \
            af[mf][1] = __float_as_uint(Asb[base + 8 * GSTR]); \
            af[mf][2] = __float_as_uint(Asb[base + 4]); \
            af[mf][3] = __float_as_uint(Asb[base + 8 * GSTR + 4]); \
        } \
        _Pragma("unroll") \
        for (int nf = 0; nf < 8; nf++) { \
            int bb = (wn + nf * 8 + gid) * GSTR + ks * 8 + tig; \
            unsigned b0 = __float_as_uint(Bsb[bb]); \
            unsigned b1 = __float_as_uint(Bsb[bb + 4]); \
            mma_tf32(acc[0][nf], af[0], b0, b1); \
            mma_tf32(acc[1][nf], af[1], b0, b1); \
        } \
    } }

    int NT = K / 16;   // 80
    ISSUE(0, 0);  CP_COMMIT();
    ISSUE(1, 16); CP_COMMIT();
    ISSUE(2, 32); CP_COMMIT();
    for (int i = 0; i < NT; i++) {
        CP_WAIT(2);
        __syncthreads();
        COMPUTE(i & 3);
        // issue-after-compute: stage (i+3)%4 == (i-1)%4 was last read in
        // compute(i-1); the barrier above guarantees all warps finished it.
        if (i + 3 < NT) ISSUE((i + 3) & 3, (i + 3) * 16);
        CP_COMMIT();   // empty groups at tail keep the wait count uniform
    }

#pragma unroll
    for (int mf = 0; mf < 2; mf++)
#pragma unroll
        for (int nf = 0; nf < 8; nf++) {
            int row = bm + wm + mf * 16 + gid;
            int col = bn + wn + nf * 8 + 2 * tig;
            float v0 = acc[mf][nf][0], v1 = acc[mf][nf][1];
            float v2 = acc[mf][nf][2], v3 = acc[mf][nf][3];
            if (rnd) { v0 = f2tff(v0); v1 = f2tff(v1); v2 = f2tff(v2); v3 = f2tff(v3); }
            *(float2*)&C[(size_t)row * N + col] = make_float2(v0, v1);
            *(float2*)&C[(size_t)(row + 8) * N + col] = make_float2(v2, v3);
        }
#undef ISSUE
#undef COMPUTE
}

// Merged QKV projection: grid (30, 64); v output tf32-rounded.
__global__ void __launch_bounds__(256) gemm_qkv(
    const float* __restrict__ A,
    float* __restrict__ q, float* __restrict__ k, float* __restrict__ v)
{
    extern __shared__ float sd[];
    int which = blockIdx.x / 10;
    int bn = (blockIdx.x % 10) * 128;
    int bm = blockIdx.y * 128;
    const float* B = (which == 0) ? g_wq : (which == 1) ? g_wk : g_wv;
    float* C = (which == 0) ? q : (which == 1) ? k : v;
    gemm_body(A, B, C, bm, bn, E_DIM, E_DIM, sd, which == 2);
}

// Single GEMM (output projection), B = g_wo, unrounded output
__global__ void __launch_bounds__(256) gemm_one(
    const float* __restrict__ A, float* __restrict__ C)
{
    extern __shared__ float sd[];
    gemm_body(A, g_wo, C, blockIdx.y * 128, blockIdx.x * 128, E_DIM, E_DIM,
              sd, false);
}

// ------------- flash attention, tf32 TC, cp.async double-buffer ----
// k, v already tf32-rounded in global -> raw 16B copies, no in-loop cvt.
#define KS_STRIDE 68
#define VS_STRIDE 72
#define ATT_STAGE_F (64 * KS_STRIDE + 64 * VS_STRIDE)   // 8960 floats
#define ATT_SMEM_BYTES (2 * ATT_STAGE_F * 4)            // 71680

__global__ void __launch_bounds__(128) attn_tf32(
    const float* __restrict__ q, const float* __restrict__ k,
    const float* __restrict__ v, float* __restrict__ o)
{
    extern __shared__ float sm[];

    int b = blockIdx.z, h = blockIdx.y, qt = blockIdx.x;
    int tid = threadIdx.x;
    int warp = tid >> 5, lane = tid & 31;
    int gid = lane >> 2, tig = lane & 3;
    int m0 = warp * 16;
    int tq0 = b * SEQ + qt * 64;

#define ATT_ISSUE(KT, S) { \
    int kt_ = (KT); int s_ = (S); \
    float* Ks_ = sm + s_ * ATT_STAGE_F; \
    float* Vs_ = Ks_ + 64 * KS_STRIDE; \
    int tk0_ = b * SEQ + kt_ * 64; \
    _Pragma("unroll") \
    for (int ii = 0; ii < 8; ii++) { \
        int idx_ = tid + ii * 128; \
        int r_ = idx_ >> 4, c4_ = (idx_ & 15) << 2; \
        const size_t goff_ = (size_t)(tk0_ + r_) * E_DIM + h * 64 + c4_; \
        cpa16(&Ks_[r_ * KS_STRIDE + c4_], &k[goff_]); \
        cpa16(&Vs_[r_ * VS_STRIDE + c4_], &v[goff_]); \
    } }

    // prologue: start tile 0, then load Q fragments while it flies
    ATT_ISSUE(0, 0); CP_COMMIT();

    unsigned qf[8][4];
    {
        const float* qp = q + (size_t)(tq0 + m0 + gid) * E_DIM + h * 64;
#pragma unroll
        for (int ks = 0; ks < 8; ks++) {
            int c = ks * 8 + tig;
            qf[ks][0] = f2tf(qp[c] * 0.125f);
            qf[ks][1] = f2tf(qp[(size_t)8 * E_DIM + c] * 0.125f);
            qf[ks][2] = f2tf(qp[c + 4] * 0.125f);
            qf[ks][3] = f2tf(qp[(size_t)8 * E_DIM + c + 4] * 0.125f);
        }
    }

    float mrow0 = -1e30f, mrow1 = -1e30f;
    float lrow0 = 0.f, lrow1 = 0.f;
    float oc[8][4];
#pragma unroll
    for (int i = 0; i < 8; i++)
#pragma unroll
        for (int j = 0; j < 4; j++) oc[i][j] = 0.f;

    for (int kt = 0; kt < SEQ / 64; kt++) {
        int cur = kt & 1;
        float* Ks = sm + cur * ATT_STAGE_F;   // K tile; becomes P after QK
        float* Vs = Ks + 64 * KS_STRIDE;

        CP_WAIT(0);          // only tile kt's group can be pending here
        __syncthreads();     // cross-thread visibility of cp.async data

        // ---- QK^T: S[16 x 64] per warp ----
        float sc[8][4];
#pragma unroll
        for (int i = 0; i < 8; i++)
#pragma unroll
            for (int j = 0; j < 4; j++) sc[i][j] = 0.f;
#pragma unroll
        for (int ks = 0; ks < 8; ks++) {
#pragma unroll
            for (int nf = 0; nf < 8; nf++) {
                int bb = (nf * 8 + gid) * KS_STRIDE + ks * 8 + tig;
                unsigned b0 = __float_as_uint(Ks[bb]);
                unsigned b1 = __float_as_uint(Ks[bb + 4]);
                mma_tf32(sc[nf], qf[ks], b0, b1);
            }
        }
        __syncthreads();     // all warps done reading Ks -> safe to write P

        // ---- online softmax ----
        float tm0 = -1e30f, tm1 = -1e30f;
#pragma unroll
        for (int nf = 0; nf < 8; nf++) {
            tm0 = fmaxf(tm0, fmaxf(sc[nf][0], sc[nf][1]));
            tm1 = fmaxf(tm1, fmaxf(sc[nf][2], sc[nf][3]));
        }
        tm0 = fmaxf(tm0, __shfl_xor_sync(0xffffffffu, tm0, 1));
        tm0 = fmaxf(tm0, __shfl_xor_sync(0xffffffffu, tm0, 2));
        tm1 = fmaxf(tm1, __shfl_xor_sync(0xffffffffu, tm1, 1));
        tm1 = fmaxf(tm1, __shfl_xor_sync(0xffffffffu, tm1, 2));
        float mn0 = fmaxf(mrow0, tm0), mn1 = fmaxf(mrow1, tm1);
        float cor0 = __expf(mrow0 - mn0), cor1 = __expf(mrow1 - mn1);
        float ls0 = 0.f, ls1 = 0.f;
#pragma unroll
        for (int nf = 0; nf < 8; nf++) {
            float p0 = __expf(sc[nf][0] - mn0);
            float p1 = __expf(sc[nf][1] - mn0);
            float p2 = __expf(sc[nf][2] - mn1);
            float p3 = __expf(sc[nf][3] - mn1);
            ls0 += p0 + p1; ls1 += p2 + p3;
            int pb = (m0 + gid) * KS_STRIDE + nf * 8 + 2 * tig;
            *(float2*)&Ks[pb] = make_float2(f2tff(p0), f2tff(p1));
            *(float2*)&Ks[pb + 8 * KS_STRIDE] = make_float2(f2tff(p2), f2tff(p3));
        }
        ls0 += __shfl_xor_sync(0xffffffffu, ls0, 1);
        ls0 += __shfl_xor_sync(0xffffffffu, ls0, 2);
        ls1 += __shfl_xor_sync(0xffffffffu, ls1, 1);
        ls1 += __shfl_xor_sync(0xffffffffu, ls1, 2);
        lrow0 = lrow0 * cor0 + ls0;
        lrow1 = lrow1 * cor1 + ls1;
        mrow0 = mn0; mrow1 = mn1;
#pragma unroll
        for (int nf = 0; nf < 8; nf++) {
            oc[nf][0] *= cor0; oc[nf][1] *= cor0;
            oc[nf][2] *= cor1; oc[nf][3] *= cor1;
        }
        __syncwarp();   // P visible to own warp (PV reads own 16 rows only)

        // ---- PV: O[16 x 64] += P[16 x 64k] * V[64k x 64] ----
#pragma unroll
        for (int ks = 0; ks < 8; ks++) {
            unsigned af[4];
            int ab = (m0 + gid) * KS_STRIDE + ks * 8 + tig;
            af[0] = __float_as_uint(Ks[ab]);
            af[1] = __float_as_uint(Ks[ab + 8 * KS_STRIDE]);
            af[2] = __float_as_uint(Ks[ab + 4]);
            af[3] = __float_as_uint(Ks[ab + 8 * KS_STRIDE + 4]);
#pragma unroll
            for (int nf = 0; nf < 8; nf++) {
                int vb = (ks * 8 + tig) * VS_STRIDE + nf * 8 + gid;
                unsigned b0 = __float_as_uint(Vs[vb]);
                unsigned b1 = __float_as_uint(Vs[vb + 4 * VS_STRIDE]);
                mma_tf32(oc[nf], af, b0, b1);
            }
        }

        // prefetch next tile into the other buffer. That buffer was last
        // read in iteration kt-1; every warp passed the top-of-kt barrier
        // (after its PV of kt-1), so WAR-safe.
        if (kt + 1 < SEQ / 64) { ATT_ISSUE(kt + 1, 1 - cur); }
        CP_COMMIT();
    }

    // o written tf32-rounded -> Wout GEMM reads raw bits
    float il0 = 1.f / lrow0, il1 = 1.f / lrow1;
    int row = tq0 + m0 + gid;
#pragma unroll
    for (int nf = 0; nf < 8; nf++) {
        int col = h * 64 + nf * 8 + 2 * tig;
        *(float2*)&o[(size_t)row * E_DIM + col] =
            make_float2(f2tff(oc[nf][0] * il0), f2tff(oc[nf][1] * il0));
        *(float2*)&o[(size_t)(row + 8) * E_DIM + col] =
            make_float2(f2tff(oc[nf][2] * il1), f2tff(oc[nf][3] * il1));
    }
#undef ATT_ISSUE
}

// -------------------------------------------------------------------
extern "C" void kernel_launch(void* const* d_in, const int* in_sizes, int n_in,
                              void* d_out, int out_size)
{
    const float* x  = (const float*)d_in[0];
    const int*   cu = (const int*)d_in[1];
    int idx = 2;
    if (in_sizes[2] == 1) idx = 3;  // skip scalar max_len if present
    const float* norm_w = (const float*)d_in[idx++];
    const float* norm_b = (const float*)d_in[idx++];
    const float* Wq     = (const float*)d_in[idx++];
    const float* Wk     = (const float*)d_in[idx++];
    const float* Wv     = (const float*)d_in[idx++];
    const float* Wout   = (const float*)d_in[idx++];
    const float* lnq_w  = (const float*)d_in[idx++];
    const float* lnk_w  = (const float*)d_in[idx++];
    float* out = (float*)d_out;

    int nb = in_sizes[1] - 1;

    float *h, *q, *k, *v, *o;
    cudaGetSymbolAddress((void**)&h, g_h);
    cudaGetSymbolAddress((void**)&q, g_q);
    cudaGetSymbolAddress((void**)&k, g_k);
    cudaGetSymbolAddress((void**)&v, g_v);
    cudaGetSymbolAddress((void**)&o, g_o);

    // opt-in dynamic smem (host-side attribute sets; not stream ops)
    cudaFuncSetAttribute(gemm_qkv, cudaFuncAttributeMaxDynamicSharedMemorySize,
                         GEMM_SMEM_BYTES);
    cudaFuncSetAttribute(gemm_one, cudaFuncAttributeMaxDynamicSharedMemorySize,
                         GEMM_SMEM_BYTES);
    cudaFuncSetAttribute(attn_tf32, cudaFuncAttributeMaxDynamicSharedMemorySize,
                         ATT_SMEM_BYTES);

    // 0) round weights to tf32 once per call
    wprep_kernel<<<dim3(E_DIM * E_DIM / 1024, 4), 256>>>(Wq, Wk, Wv, Wout);

    // 1) pre-norm (tf32-rounded output) + rope table
    ln_kernel<<<T_TOK, 256>>>(x, norm_w, norm_b, h);
    rope_table_kernel<<<T_TOK / 8, 256>>>(cu, nb);

    // 2) merged Q/K/V projections (4-stage pipeline; v rounded)
    gemm_qkv<<<dim3(30, T_TOK / 128), 256, GEMM_SMEM_BYTES>>>(h, q, k, v);

    // 3) q/k LayerNorm + RoPE (in place, rounded output)
    lnrope_kernel<<<dim3(T_TOK, 2), 256>>>(q, k, lnq_w, lnk_w);

    // 4) attention (double-buffered K/V, rounded o output)
    dim3 agrid(SEQ / 64, NHEAD, NBATCH);
    attn_tf32<<<agrid, 128, ATT_SMEM_BYTES>>>(q, k, v, o);

    // 5) output projection
    gemm_one<<<dim3(E_DIM / 128, T_TOK / 128), 256, GEMM_SMEM_BYTES>>>(o, out);
}

// round 8
// speedup vs baseline: 7.1252x; 1.0624x over previous
#include <cuda_runtime.h>
#include <math.h>

#define E_DIM 1280
#define NHEAD 20
#define DHEAD 64
#define T_TOK 8192
#define SEQ   1024
#define NBATCH 8

// ---------------- scratch (no allocations allowed) ----------------
__device__ float g_h[T_TOK * E_DIM];
__device__ float g_q[T_TOK * E_DIM];
__device__ float g_k[T_TOK * E_DIM];
__device__ float g_v[T_TOK * E_DIM];
__device__ float g_o[T_TOK * E_DIM];
__device__ float g_wq[E_DIM * E_DIM];
__device__ float g_wk[E_DIM * E_DIM];
__device__ float g_wv[E_DIM * E_DIM];
__device__ float g_wo[E_DIM * E_DIM];
__device__ float g_cos[T_TOK * 32];
__device__ float g_sin[T_TOK * 32];

// ---------------- helpers ----------------
__device__ __forceinline__ unsigned f2tf(float f) {
    unsigned u;
    asm("cvt.rna.tf32.f32 %0, %1;" : "=r"(u) : "f"(f));
    return u;
}
__device__ __forceinline__ float f2tff(float f) {
    return __uint_as_float(f2tf(f));
}

__device__ __forceinline__ void mma_tf32(float c[4], const unsigned a[4],
                                         unsigned b0, unsigned b1) {
    asm volatile(
        "mma.sync.aligned.m16n8k8.row.col.f32.tf32.tf32.f32 "
        "{%0,%1,%2,%3}, {%4,%5,%6,%7}, {%8,%9}, {%0,%1,%2,%3};\n"
        : "+f"(c[0]), "+f"(c[1]), "+f"(c[2]), "+f"(c[3])
        : "r"(a[0]), "r"(a[1]), "r"(a[2]), "r"(a[3]), "r"(b0), "r"(b1));
}

__device__ __forceinline__ void cpa16(void* s, const void* g) {
    unsigned saddr = (unsigned)__cvta_generic_to_shared(s);
    asm volatile("cp.async.ca.shared.global [%0], [%1], 16;\n"
                 :: "r"(saddr), "l"(g));
}
#define CP_COMMIT() asm volatile("cp.async.commit_group;\n" ::: "memory")
#define CP_WAIT(N)  asm volatile("cp.async.wait_group " #N ";\n" ::: "memory")

// ------------- weight prep: round to tf32 in global ---------------
__global__ void __launch_bounds__(256) wprep_kernel(
    const float* __restrict__ Wq, const float* __restrict__ Wk,
    const float* __restrict__ Wv, const float* __restrict__ Wo)
{
    const float* src = (blockIdx.y == 0) ? Wq : (blockIdx.y == 1) ? Wk :
                       (blockIdx.y == 2) ? Wv : Wo;
    float* dst = (blockIdx.y == 0) ? g_wq : (blockIdx.y == 1) ? g_wk :
                 (blockIdx.y == 2) ? g_wv : g_wo;
    int i = (blockIdx.x * 256 + threadIdx.x) * 4;
    float4 v = *(const float4*)&src[i];
    *(float4*)&dst[i] = make_float4(f2tff(v.x), f2tff(v.y), f2tff(v.z), f2tff(v.w));
}

// ---------------- LayerNorm (with bias) : x -> h (tf32-rounded) ----
__global__ void __launch_bounds__(256) ln_kernel(
    const float* __restrict__ x, const float* __restrict__ w,
    const float* __restrict__ b, float* __restrict__ out)
{
    int t = blockIdx.x;
    const float* xr = x + (size_t)t * E_DIM;
    float vals[5];
    float s = 0.f, s2 = 0.f;
#pragma unroll
    for (int j = 0; j < 5; j++) {
        float v = xr[threadIdx.x + j * 256];
        vals[j] = v; s += v; s2 += v * v;
    }
    __shared__ float red0[8], red1[8];
    int lane = threadIdx.x & 31, wid = threadIdx.x >> 5;
#pragma unroll
    for (int o = 16; o; o >>= 1) {
        s  += __shfl_xor_sync(0xffffffffu, s,  o);
        s2 += __shfl_xor_sync(0xffffffffu, s2, o);
    }
    if (lane == 0) { red0[wid] = s; red1[wid] = s2; }
    __syncthreads();
    float ts = 0.f, ts2 = 0.f;
#pragma unroll
    for (int j = 0; j < 8; j++) { ts += red0[j]; ts2 += red1[j]; }
    float mean = ts * (1.f / E_DIM);
    float var  = ts2 * (1.f / E_DIM) - mean * mean;
    float rstd = rsqrtf(var + 1e-5f);
    float* orow = out + (size_t)t * E_DIM;
#pragma unroll
    for (int j = 0; j < 5; j++) {
        int idx = threadIdx.x + j * 256;
        orow[idx] = f2tff((vals[j] - mean) * rstd * w[idx] + b[idx]);
    }
}

// ---------------- RoPE table: cos/sin per (token, freq) ------------
__global__ void __launch_bounds__(256) rope_table_kernel(
    const int* __restrict__ cu, int nb)
{
    int t = blockIdx.x * 8 + (threadIdx.x >> 5);
    int f = threadIdx.x & 31;
    int seg = 0;
    for (int bb = 1; bb < nb; bb++) if (t >= cu[bb]) seg = bb;
    float pos = (float)(t - cu[seg]);
    const float kfreq = -0.2878231366f; // -ln(10000)/32
    float ang = pos * __expf((float)f * kfreq);
    float sn, c;
    sincosf(ang, &sn, &c);
    g_cos[t * 32 + f] = c;
    g_sin[t * 32 + f] = sn;
}

// ------------- LayerNorm (no bias) + RoPE, in place (rounded) ------
__global__ void __launch_bounds__(256) lnrope_kernel(
    float* __restrict__ q, float* __restrict__ k,
    const float* __restrict__ wq, const float* __restrict__ wk)
{
    int t = blockIdx.x;
    int part = blockIdx.y;
    __shared__ float sb[E_DIM];
    __shared__ float red0[8], red1[8];
    __shared__ float s_stats[2];
    int lane = threadIdx.x & 31, wid = threadIdx.x >> 5;

    float* base = (part ? k : q) + (size_t)t * E_DIM;
    const float* w = part ? wk : wq;
    float s = 0.f, s2 = 0.f;
    for (int i = threadIdx.x; i < E_DIM; i += 256) {
        float v = base[i];
        sb[i] = v; s += v; s2 += v * v;
    }
#pragma unroll
    for (int o = 16; o; o >>= 1) {
        s  += __shfl_xor_sync(0xffffffffu, s,  o);
        s2 += __shfl_xor_sync(0xffffffffu, s2, o);
    }
    if (lane == 0) { red0[wid] = s; red1[wid] = s2; }
    __syncthreads();
    if (threadIdx.x == 0) {
        float ts = 0.f, ts2 = 0.f;
#pragma unroll
        for (int j = 0; j < 8; j++) { ts += red0[j]; ts2 += red1[j]; }
        float mean = ts * (1.f / E_DIM);
        float var  = ts2 * (1.f / E_DIM) - mean * mean;
        s_stats[0] = mean;
        s_stats[1] = rsqrtf(var + 1e-5f);
    }
    __syncthreads();
    float mean = s_stats[0], rstd = s_stats[1];
    for (int i = threadIdx.x; i < E_DIM; i += 256) {
        int ld = i & 63;
        float xn = (sb[i] - mean) * rstd * w[i];
        int pi = (ld < 32) ? (i + 32) : (i - 32);
        float pn = (sb[pi] - mean) * rstd * w[pi];
        int fi = ld & 31;
        float c  = g_cos[t * 32 + fi];
        float sn = g_sin[t * 32 + fi];
        float rot = (ld < 32) ? -pn : pn;
        base[i] = f2tff(xn * c + rot * sn);
    }
}

// ------------- tf32 GEMM core, 4-stage cp.async pipeline -----------
// 128 threads (4 warps, 2x2), warp tile 64x64 -> A/B smem redundancy 2x
// (was 2x/4x with 32x64 tiles): flops per smem byte 10.7 -> 16.
// Operands PRE-ROUNDED to tf32 in global. One __syncthreads per k-tile.
#define GSTR 20
#define GSTAGE_F (2 * 128 * GSTR)            // floats per stage (A then B)
#define GEMM_SMEM_BYTES (4 * GSTAGE_F * 4)   // 81920

__device__ __forceinline__ void gemm_body(
    const float* __restrict__ A, const float* __restrict__ B,
    float* __restrict__ C, int bm, int bn, int N, int K,
    float* sd, bool rnd)
{
    int tid = threadIdx.x, lane = tid & 31, warp = tid >> 5;
    int gid = lane >> 2, tig = lane & 3;
    int wm = (warp >> 1) * 64, wn = (warp & 1) * 64;

    float acc[4][8][4];
#pragma unroll
    for (int i = 0; i < 4; i++)
#pragma unroll
        for (int j = 0; j < 8; j++)
#pragma unroll
            for (int l = 0; l < 4; l++) acc[i][j][l] = 0.f;

    int lr = tid >> 2;           // 0..31
    int lc = (tid & 3) << 2;     // 0,4,8,12
    const float* Ap = A + (size_t)(bm + lr) * K + lc;
    const float* Bp = B + (size_t)(bn + lr) * K + lc;

#define ISSUE(S, K0) { \
    int s_ = (S); int k0_ = (K0); \
    float* As_ = sd + s_ * GSTAGE_F; \
    float* Bs_ = As_ + 128 * GSTR; \
    _Pragma("unroll") \
    for (int ii = 0; ii < 4; ii++) { \
        int row = lr + ii * 32; \
        cpa16(&As_[row * GSTR + lc], Ap + (size_t)ii * 32 * K + k0_); \
        cpa16(&Bs_[row * GSTR + lc], Bp + (size_t)ii * 32 * K + k0_); \
    } }

#define COMPUTE(S) { \
    const float* Asb = sd + (S) * GSTAGE_F; \
    const float* Bsb = Asb + 128 * GSTR; \
    _Pragma("unroll") \
    for (int ks = 0; ks < 2; ks++) { \
        unsigned af[4][4]; \
        _Pragma("unroll") \
        for (int mf = 0; mf < 4; mf++) { \
            int base = (wm + mf * 16 + gid) * GSTR + ks * 8 + tig; \
            af[mf][0] = __float_as_uint(Asb[base]); \
            af[mf][1] = __float_as_uint(Asb[base + 8 * GSTR]); \
            af[mf][2] = __float_as_uint(Asb[base + 4]); \
            af[mf][3] = __float_as_uint(Asb[base + 8 * GSTR + 4]); \
        } \
        _Pragma("unroll") \
        for (int nf = 0; nf < 8; nf++) { \
            int bb = (wn + nf * 8 + gid) * GSTR + ks * 8 + tig; \
            unsigned b0 = __float_as_uint(Bsb[bb]); \
            unsigned b1 = __float_as_uint(Bsb[bb + 4]); \
            mma_tf32(acc[0][nf], af[0], b0, b1); \
            mma_tf32(acc[1][nf], af[1], b0, b1); \
            mma_tf32(acc[2][nf], af[2], b0, b1); \
            mma_tf32(acc[3][nf], af[3], b0, b1); \
        } \
    } }

    int NT = K / 16;   // 80
    ISSUE(0, 0);  CP_COMMIT();
    ISSUE(1, 16); CP_COMMIT();
    ISSUE(2, 32); CP_COMMIT();
    for (int i = 0; i < NT; i++) {
        CP_WAIT(2);
        __syncthreads();
        COMPUTE(i & 3);
        // stage (i+3)%4 == (i-1)%4 was last read in compute(i-1);
        // the barrier above guarantees all warps finished it.
        if (i + 3 < NT) ISSUE((i + 3) & 3, (i + 3) * 16);
        CP_COMMIT();   // empty groups at tail keep the wait count uniform
    }

#pragma unroll
    for (int mf = 0; mf < 4; mf++)
#pragma unroll
        for (int nf = 0; nf < 8; nf++) {
            int row = bm + wm + mf * 16 + gid;
            int col = bn + wn + nf * 8 + 2 * tig;
            float v0 = acc[mf][nf][0], v1 = acc[mf][nf][1];
            float v2 = acc[mf][nf][2], v3 = acc[mf][nf][3];
            if (rnd) { v0 = f2tff(v0); v1 = f2tff(v1); v2 = f2tff(v2); v3 = f2tff(v3); }
            *(float2*)&C[(size_t)row * N + col] = make_float2(v0, v1);
            *(float2*)&C[(size_t)(row + 8) * N + col] = make_float2(v2, v3);
        }
#undef ISSUE
#undef COMPUTE
}

// Merged QKV projection: grid (30, 64); v output tf32-rounded.
__global__ void __launch_bounds__(128) gemm_qkv(
    const float* __restrict__ A,
    float* __restrict__ q, float* __restrict__ k, float* __restrict__ v)
{
    extern __shared__ float sd[];
    int which = blockIdx.x / 10;
    int bn = (blockIdx.x % 10) * 128;
    int bm = blockIdx.y * 128;
    const float* B = (which == 0) ? g_wq : (which == 1) ? g_wk : g_wv;
    float* C = (which == 0) ? q : (which == 1) ? k : v;
    gemm_body(A, B, C, bm, bn, E_DIM, E_DIM, sd, which == 2);
}

// Single GEMM (output projection), B = g_wo, unrounded output
__global__ void __launch_bounds__(128) gemm_one(
    const float* __restrict__ A, float* __restrict__ C)
{
    extern __shared__ float sd[];
    gemm_body(A, g_wo, C, blockIdx.y * 128, blockIdx.x * 128, E_DIM, E_DIM,
              sd, false);
}

// ------------- flash attention, tf32 TC, cp.async double-buffer ----
// k, v already tf32-rounded in global -> raw 16B copies, no in-loop cvt.
#define KS_STRIDE 68
#define VS_STRIDE 72
#define ATT_STAGE_F (64 * KS_STRIDE + 64 * VS_STRIDE)   // 8960 floats
#define ATT_SMEM_BYTES (2 * ATT_STAGE_F * 4)            // 71680

__global__ void __launch_bounds__(128) attn_tf32(
    const float* __restrict__ q, const float* __restrict__ k,
    const float* __restrict__ v, float* __restrict__ o)
{
    extern __shared__ float sm[];

    int b = blockIdx.z, h = blockIdx.y, qt = blockIdx.x;
    int tid = threadIdx.x;
    int warp = tid >> 5, lane = tid & 31;
    int gid = lane >> 2, tig = lane & 3;
    int m0 = warp * 16;
    int tq0 = b * SEQ + qt * 64;

#define ATT_ISSUE(KT, S) { \
    int kt_ = (KT); int s_ = (S); \
    float* Ks_ = sm + s_ * ATT_STAGE_F; \
    float* Vs_ = Ks_ + 64 * KS_STRIDE; \
    int tk0_ = b * SEQ + kt_ * 64; \
    _Pragma("unroll") \
    for (int ii = 0; ii < 8; ii++) { \
        int idx_ = tid + ii * 128; \
        int r_ = idx_ >> 4, c4_ = (idx_ & 15) << 2; \
        const size_t goff_ = (size_t)(tk0_ + r_) * E_DIM + h * 64 + c4_; \
        cpa16(&Ks_[r_ * KS_STRIDE + c4_], &k[goff_]); \
        cpa16(&Vs_[r_ * VS_STRIDE + c4_], &v[goff_]); \
    } }

    // prologue: start tile 0, then load Q fragments while it flies
    ATT_ISSUE(0, 0); CP_COMMIT();

    unsigned qf[8][4];
    {
        const float* qp = q + (size_t)(tq0 + m0 + gid) * E_DIM + h * 64;
#pragma unroll
        for (int ks = 0; ks < 8; ks++) {
            int c = ks * 8 + tig;
            qf[ks][0] = f2tf(qp[c] * 0.125f);
            qf[ks][1] = f2tf(qp[(size_t)8 * E_DIM + c] * 0.125f);
            qf[ks][2] = f2tf(qp[c + 4] * 0.125f);
            qf[ks][3] = f2tf(qp[(size_t)8 * E_DIM + c + 4] * 0.125f);
        }
    }

    float mrow0 = -1e30f, mrow1 = -1e30f;
    float lrow0 = 0.f, lrow1 = 0.f;
    float oc[8][4];
#pragma unroll
    for (int i = 0; i < 8; i++)
#pragma unroll
        for (int j = 0; j < 4; j++) oc[i][j] = 0.f;

    for (int kt = 0; kt < SEQ / 64; kt++) {
        int cur = kt & 1;
        float* Ks = sm + cur * ATT_STAGE_F;   // K tile; becomes P after QK
        float* Vs = Ks + 64 * KS_STRIDE;

        CP_WAIT(0);          // only tile kt's group can be pending here
        __syncthreads();     // cross-thread visibility of cp.async data

        // ---- QK^T: S[16 x 64] per warp ----
        float sc[8][4];
#pragma unroll
        for (int i = 0; i < 8; i++)
#pragma unroll
            for (int j = 0; j < 4; j++) sc[i][j] = 0.f;
#pragma unroll
        for (int ks = 0; ks < 8; ks++) {
#pragma unroll
            for (int nf = 0; nf < 8; nf++) {
                int bb = (nf * 8 + gid) * KS_STRIDE + ks * 8 + tig;
                unsigned b0 = __float_as_uint(Ks[bb]);
                unsigned b1 = __float_as_uint(Ks[bb + 4]);
                mma_tf32(sc[nf], qf[ks], b0, b1);
            }
        }
        __syncthreads();     // all warps done reading Ks -> safe to write P

        // ---- online softmax ----
        float tm0 = -1e30f, tm1 = -1e30f;
#pragma unroll
        for (int nf = 0; nf < 8; nf++) {
            tm0 = fmaxf(tm0, fmaxf(sc[nf][0], sc[nf][1]));
            tm1 = fmaxf(tm1, fmaxf(sc[nf][2], sc[nf][3]));
        }
        tm0 = fmaxf(tm0, __shfl_xor_sync(0xffffffffu, tm0, 1));
        tm0 = fmaxf(tm0, __shfl_xor_sync(0xffffffffu, tm0, 2));
        tm1 = fmaxf(tm1, __shfl_xor_sync(0xffffffffu, tm1, 1));
        tm1 = fmaxf(tm1, __shfl_xor_sync(0xffffffffu, tm1, 2));
        float mn0 = fmaxf(mrow0, tm0), mn1 = fmaxf(mrow1, tm1);
        float cor0 = __expf(mrow0 - mn0), cor1 = __expf(mrow1 - mn1);
        float ls0 = 0.f, ls1 = 0.f;
#pragma unroll
        for (int nf = 0; nf < 8; nf++) {
            float p0 = __expf(sc[nf][0] - mn0);
            float p1 = __expf(sc[nf][1] - mn0);
            float p2 = __expf(sc[nf][2] - mn1);
            float p3 = __expf(sc[nf][3] - mn1);
            ls0 += p0 + p1; ls1 += p2 + p3;
            int pb = (m0 + gid) * KS_STRIDE + nf * 8 + 2 * tig;
            *(float2*)&Ks[pb] = make_float2(f2tff(p0), f2tff(p1));
            *(float2*)&Ks[pb + 8 * KS_STRIDE] = make_float2(f2tff(p2), f2tff(p3));
        }
        ls0 += __shfl_xor_sync(0xffffffffu, ls0, 1);
        ls0 += __shfl_xor_sync(0xffffffffu, ls0, 2);
        ls1 += __shfl_xor_sync(0xffffffffu, ls1, 1);
        ls1 += __shfl_xor_sync(0xffffffffu, ls1, 2);
        lrow0 = lrow0 * cor0 + ls0;
        lrow1 = lrow1 * cor1 + ls1;
        mrow0 = mn0; mrow1 = mn1;
#pragma unroll
        for (int nf = 0; nf < 8; nf++) {
            oc[nf][0] *= cor0; oc[nf][1] *= cor0;
            oc[nf][2] *= cor1; oc[nf][3] *= cor1;
        }
        __syncwarp();   // P visible to own warp (PV reads own 16 rows only)

        // ---- PV: O[16 x 64] += P[16 x 64k] * V[64k x 64] ----
#pragma unroll
        for (int ks = 0; ks < 8; ks++) {
            unsigned af[4];
            int ab = (m0 + gid) * KS_STRIDE + ks * 8 + tig;
            af[0] = __float_as_uint(Ks[ab]);
            af[1] = __float_as_uint(Ks[ab + 8 * KS_STRIDE]);
            af[2] = __float_as_uint(Ks[ab + 4]);
            af[3] = __float_as_uint(Ks[ab + 8 * KS_STRIDE + 4]);
#pragma unroll
            for (int nf = 0; nf < 8; nf++) {
                int vb = (ks * 8 + tig) * VS_STRIDE + nf * 8 + gid;
                unsigned b0 = __float_as_uint(Vs[vb]);
                unsigned b1 = __float_as_uint(Vs[vb + 4 * VS_STRIDE]);
                mma_tf32(oc[nf], af, b0, b1);
            }
        }

        // prefetch next tile into the other buffer. That buffer was last
        // read in iteration kt-1; every warp passed the top-of-kt barrier
        // (after its PV of kt-1), so WAR-safe.
        if (kt + 1 < SEQ / 64) { ATT_ISSUE(kt + 1, 1 - cur); }
        CP_COMMIT();
    }

    // o written tf32-rounded -> Wout GEMM reads raw bits
    float il0 = 1.f / lrow0, il1 = 1.f / lrow1;
    int row = tq0 + m0 + gid;
#pragma unroll
    for (int nf = 0; nf < 8; nf++) {
        int col = h * 64 + nf * 8 + 2 * tig;
        *(float2*)&o[(size_t)row * E_DIM + col] =
            make_float2(f2tff(oc[nf][0] * il0), f2tff(oc[nf][1] * il0));
        *(float2*)&o[(size_t)(row + 8) * E_DIM + col] =
            make_float2(f2tff(oc[nf][2] * il1), f2tff(oc[nf][3] * il1));
    }
#undef ATT_ISSUE
}

// -------------------------------------------------------------------
extern "C" void kernel_launch(void* const* d_in, const int* in_sizes, int n_in,
                              void* d_out, int out_size)
{
    const float* x  = (const float*)d_in[0];
    const int*   cu = (const int*)d_in[1];
    int idx = 2;
    if (in_sizes[2] == 1) idx = 3;  // skip scalar max_len if present
    const float* norm_w = (const float*)d_in[idx++];
    const float* norm_b = (const float*)d_in[idx++];
    const float* Wq     = (const float*)d_in[idx++];
    const float* Wk     = (const float*)d_in[idx++];
    const float* Wv     = (const float*)d_in[idx++];
    const float* Wout   = (const float*)d_in[idx++];
    const float* lnq_w  = (const float*)d_in[idx++];
    const float* lnk_w  = (const float*)d_in[idx++];
    float* out = (float*)d_out;

    int nb = in_sizes[1] - 1;

    float *h, *q, *k, *v, *o;
    cudaGetSymbolAddress((void**)&h, g_h);
    cudaGetSymbolAddress((void**)&q, g_q);
    cudaGetSymbolAddress((void**)&k, g_k);
    cudaGetSymbolAddress((void**)&v, g_v);
    cudaGetSymbolAddress((void**)&o, g_o);

    // opt-in dynamic smem (host-side attribute sets; not stream ops)
    cudaFuncSetAttribute(gemm_qkv, cudaFuncAttributeMaxDynamicSharedMemorySize,
                         GEMM_SMEM_BYTES);
    cudaFuncSetAttribute(gemm_one, cudaFuncAttributeMaxDynamicSharedMemorySize,
                         GEMM_SMEM_BYTES);
    cudaFuncSetAttribute(attn_tf32, cudaFuncAttributeMaxDynamicSharedMemorySize,
                         ATT_SMEM_BYTES);

    // 0) round weights to tf32 once per call
    wprep_kernel<<<dim3(E_DIM * E_DIM / 1024, 4), 256>>>(Wq, Wk, Wv, Wout);

    // 1) pre-norm (tf32-rounded output) + rope table
    ln_kernel<<<T_TOK, 256>>>(x, norm_w, norm_b, h);
    rope_table_kernel<<<T_TOK / 8, 256>>>(cu, nb);

    // 2) merged Q/K/V projections (64x64 warp tiles, 4-stage pipeline)
    gemm_qkv<<<dim3(30, T_TOK / 128), 128, GEMM_SMEM_BYTES>>>(h, q, k, v);

    // 3) q/k LayerNorm + RoPE (in place, rounded output)
    lnrope_kernel<<<dim3(T_TOK, 2), 256>>>(q, k, lnq_w, lnk_w);

    // 4) attention (double-buffered K/V, rounded o output)
    dim3 agrid(SEQ / 64, NHEAD, NBATCH);
    attn_tf32<<<agrid, 128, ATT_SMEM_BYTES>>>(q, k, v, o);

    // 5) output projection
    gemm_one<<<dim3(E_DIM / 128, T_TOK / 128), 128, GEMM_SMEM_BYTES>>>(o, out);
}

// round 10
// speedup vs baseline: 7.4429x; 1.0446x over previous
#include <cuda_runtime.h>
#include <math.h>

#define E_DIM 1280
#define NHEAD 20
#define DHEAD 64
#define T_TOK 8192
#define SEQ   1024
#define NBATCH 8

// ---------------- scratch (no allocations allowed) ----------------
__device__ float g_h[T_TOK * E_DIM];
__device__ float g_q[T_TOK * E_DIM];
__device__ float g_k[T_TOK * E_DIM];
__device__ float g_v[T_TOK * E_DIM];
__device__ float g_o[T_TOK * E_DIM];
__device__ float g_wq[E_DIM * E_DIM];
__device__ float g_wk[E_DIM * E_DIM];
__device__ float g_wv[E_DIM * E_DIM];
__device__ float g_wo[E_DIM * E_DIM];
__device__ float g_cos[T_TOK * 32];
__device__ float g_sin[T_TOK * 32];

// ---------------- helpers ----------------
__device__ __forceinline__ unsigned f2tf(float f) {
    unsigned u;
    asm("cvt.rna.tf32.f32 %0, %1;" : "=r"(u) : "f"(f));
    return u;
}
__device__ __forceinline__ float f2tff(float f) {
    return __uint_as_float(f2tf(f));
}

__device__ __forceinline__ void mma_tf32(float c[4], const unsigned a[4],
                                         unsigned b0, unsigned b1) {
    asm volatile(
        "mma.sync.aligned.m16n8k8.row.col.f32.tf32.tf32.f32 "
        "{%0,%1,%2,%3}, {%4,%5,%6,%7}, {%8,%9}, {%0,%1,%2,%3};\n"
        : "+f"(c[0]), "+f"(c[1]), "+f"(c[2]), "+f"(c[3])
        : "r"(a[0]), "r"(a[1]), "r"(a[2]), "r"(a[3]), "r"(b0), "r"(b1));
}

__device__ __forceinline__ void cpa16(void* s, const void* g) {
    unsigned saddr = (unsigned)__cvta_generic_to_shared(s);
    asm volatile("cp.async.ca.shared.global [%0], [%1], 16;\n"
                 :: "r"(saddr), "l"(g));
}
#define CP_COMMIT() asm volatile("cp.async.commit_group;\n" ::: "memory")
#define CP_WAIT(N)  asm volatile("cp.async.wait_group " #N ";\n" ::: "memory")

// ------------- weight prep: round to tf32 in global ---------------
__global__ void __launch_bounds__(256) wprep_kernel(
    const float* __restrict__ Wq, const float* __restrict__ Wk,
    const float* __restrict__ Wv, const float* __restrict__ Wo)
{
    const float* src = (blockIdx.y == 0) ? Wq : (blockIdx.y == 1) ? Wk :
                       (blockIdx.y == 2) ? Wv : Wo;
    float* dst = (blockIdx.y == 0) ? g_wq : (blockIdx.y == 1) ? g_wk :
                 (blockIdx.y == 2) ? g_wv : g_wo;
    int i = (blockIdx.x * 256 + threadIdx.x) * 4;
    float4 v = *(const float4*)&src[i];
    *(float4*)&dst[i] = make_float4(f2tff(v.x), f2tff(v.y), f2tff(v.z), f2tff(v.w));
}

// ---------------- LayerNorm (with bias) : x -> h (tf32-rounded) ----
__global__ void __launch_bounds__(256) ln_kernel(
    const float* __restrict__ x, const float* __restrict__ w,
    const float* __restrict__ b, float* __restrict__ out)
{
    int t = blockIdx.x;
    const float* xr = x + (size_t)t * E_DIM;
    float vals[5];
    float s = 0.f, s2 = 0.f;
#pragma unroll
    for (int j = 0; j < 5; j++) {
        float v = xr[threadIdx.x + j * 256];
        vals[j] = v; s += v; s2 += v * v;
    }
    __shared__ float red0[8], red1[8];
    int lane = threadIdx.x & 31, wid = threadIdx.x >> 5;
#pragma unroll
    for (int o = 16; o; o >>= 1) {
        s  += __shfl_xor_sync(0xffffffffu, s,  o);
        s2 += __shfl_xor_sync(0xffffffffu, s2, o);
    }
    if (lane == 0) { red0[wid] = s; red1[wid] = s2; }
    __syncthreads();
    float ts = 0.f, ts2 = 0.f;
#pragma unroll
    for (int j = 0; j < 8; j++) { ts += red0[j]; ts2 += red1[j]; }
    float mean = ts * (1.f / E_DIM);
    float var  = ts2 * (1.f / E_DIM) - mean * mean;
    float rstd = rsqrtf(var + 1e-5f);
    float* orow = out + (size_t)t * E_DIM;
#pragma unroll
    for (int j = 0; j < 5; j++) {
        int idx = threadIdx.x + j * 256;
        orow[idx] = f2tff((vals[j] - mean) * rstd * w[idx] + b[idx]);
    }
}

// ---------------- RoPE table: cos/sin per (token, freq) ------------
__global__ void __launch_bounds__(256) rope_table_kernel(
    const int* __restrict__ cu, int nb)
{
    int t = blockIdx.x * 8 + (threadIdx.x >> 5);
    int f = threadIdx.x & 31;
    int seg = 0;
    for (int bb = 1; bb < nb; bb++) if (t >= cu[bb]) seg = bb;
    float pos = (float)(t - cu[seg]);
    const float kfreq = -0.2878231366f; // -ln(10000)/32
    float ang = pos * __expf((float)f * kfreq);
    float sn, c;
    sincosf(ang, &sn, &c);
    g_cos[t * 32 + f] = c;
    g_sin[t * 32 + f] = sn;
}

// ------------- LayerNorm (no bias) + RoPE, in place (rounded) ------
__global__ void __launch_bounds__(256) lnrope_kernel(
    float* __restrict__ q, float* __restrict__ k,
    const float* __restrict__ wq, const float* __restrict__ wk)
{
    int t = blockIdx.x;
    int part = blockIdx.y;
    __shared__ float sb[E_DIM];
    __shared__ float red0[8], red1[8];
    __shared__ float s_stats[2];
    int lane = threadIdx.x & 31, wid = threadIdx.x >> 5;

    float* base = (part ? k : q) + (size_t)t * E_DIM;
    const float* w = part ? wk : wq;
    float s = 0.f, s2 = 0.f;
    for (int i = threadIdx.x; i < E_DIM; i += 256) {
        float v = base[i];
        sb[i] = v; s += v; s2 += v * v;
    }
#pragma unroll
    for (int o = 16; o; o >>= 1) {
        s  += __shfl_xor_sync(0xffffffffu, s,  o);
        s2 += __shfl_xor_sync(0xffffffffu, s2, o);
    }
    if (lane == 0) { red0[wid] = s; red1[wid] = s2; }
    __syncthreads();
    if (threadIdx.x == 0) {
        float ts = 0.f, ts2 = 0.f;
#pragma unroll
        for (int j = 0; j < 8; j++) { ts += red0[j]; ts2 += red1[j]; }
        float mean = ts * (1.f / E_DIM);
        float var  = ts2 * (1.f / E_DIM) - mean * mean;
        s_stats[0] = mean;
        s_stats[1] = rsqrtf(var + 1e-5f);
    }
    __syncthreads();
    float mean = s_stats[0], rstd = s_stats[1];
    for (int i = threadIdx.x; i < E_DIM; i += 256) {
        int ld = i & 63;
        float xn = (sb[i] - mean) * rstd * w[i];
        int pi = (ld < 32) ? (i + 32) : (i - 32);
        float pn = (sb[pi] - mean) * rstd * w[pi];
        int fi = ld & 31;
        float c  = g_cos[t * 32 + fi];
        float sn = g_sin[t * 32 + fi];
        float rot = (ld < 32) ? -pn : pn;
        base[i] = f2tff(xn * c + rot * sn);
    }
}

// ------------- tf32 GEMM core, 3-stage cp.async pipeline -----------
// 128 threads (4 warps, 2x2), warp tile 64x64. 3 stages x 20KB = 60KB
// smem -> 3 CTAs/SM (12 warps/SM, was 8): hides the LDS latency that
// bound R8. __launch_bounds__(128,3) caps regs at 170 (have 164).
#define GSTR 20
#define GSTAGE_F (2 * 128 * GSTR)            // floats per stage (A then B)
#define GEMM_SMEM_BYTES (3 * GSTAGE_F * 4)   // 61440

__device__ __forceinline__ void gemm_body(
    const float* __restrict__ A, const float* __restrict__ B,
    float* __restrict__ C, int bm, int bn, int N, int K,
    float* sd, bool rnd)
{
    int tid = threadIdx.x, lane = tid & 31, warp = tid >> 5;
    int gid = lane >> 2, tig = lane & 3;
    int wm = (warp >> 1) * 64, wn = (warp & 1) * 64;

    float acc[4][8][4];
#pragma unroll
    for (int i = 0; i < 4; i++)
#pragma unroll
        for (int j = 0; j < 8; j++)
#pragma unroll
            for (int l = 0; l < 4; l++) acc[i][j][l] = 0.f;

    int lr = tid >> 2;           // 0..31
    int lc = (tid & 3) << 2;     // 0,4,8,12
    const float* Ap = A + (size_t)(bm + lr) * K + lc;
    const float* Bp = B + (size_t)(bn + lr) * K + lc;

#define ISSUE(S, K0) { \
    int s_ = (S); int k0_ = (K0); \
    float* As_ = sd + s_ * GSTAGE_F; \
    float* Bs_ = As_ + 128 * GSTR; \
    _Pragma("unroll") \
    for (int ii = 0; ii < 4; ii++) { \
        int row = lr + ii * 32; \
        cpa16(&As_[row * GSTR + lc], Ap + (size_t)ii * 32 * K + k0_); \
        cpa16(&Bs_[row * GSTR + lc], Bp + (size_t)ii * 32 * K + k0_); \
    } }

#define COMPUTE(S) { \
    const float* Asb = sd + (S) * GSTAGE_F; \
    const float* Bsb = Asb + 128 * GSTR; \
    _Pragma("unroll") \
    for (int ks = 0; ks < 2; ks++) { \
        unsigned af[4][4]; \
        _Pragma("unroll") \
        for (int mf = 0; mf < 4; mf++) { \
            int base = (wm + mf * 16 + gid) * GSTR + ks * 8 + tig; \
            af[mf][0] = __float_as_uint(Asb[base]); \
            af[mf][1] = __float_as_uint(Asb[base + 8 * GSTR]); \
            af[mf][2] = __float_as_uint(Asb[base + 4]); \
            af[mf][3] = __float_as_uint(Asb[base + 8 * GSTR + 4]); \
        } \
        _Pragma("unroll") \
        for (int nf = 0; nf < 8; nf++) { \
            int bb = (wn + nf * 8 + gid) * GSTR + ks * 8 + tig; \
            unsigned b0 = __float_as_uint(Bsb[bb]); \
            unsigned b1 = __float_as_uint(Bsb[bb + 4]); \
            mma_tf32(acc[0][nf], af[0], b0, b1); \
            mma_tf32(acc[1][nf], af[1], b0, b1); \
            mma_tf32(acc[2][nf], af[2], b0, b1); \
            mma_tf32(acc[3][nf], af[3], b0, b1); \
        } \
    } }

    int NT = K / 16;   // 80
    ISSUE(0, 0);  CP_COMMIT();
    ISSUE(1, 16); CP_COMMIT();
    int cs = 0;        // compute stage = i % 3
    for (int i = 0; i < NT; i++) {
        CP_WAIT(1);
        __syncthreads();
        COMPUTE(cs);
        // stage (i+2)%3 == (i-1)%3 was last read in compute(i-1);
        // the barrier above guarantees all warps finished it.
        if (i + 2 < NT) {
            int ns = cs - 1; if (ns < 0) ns = 2;   // (i+2)%3
            ISSUE(ns, (i + 2) * 16);
        }
        CP_COMMIT();   // empty groups at tail keep the wait count uniform
        cs = (cs == 2) ? 0 : cs + 1;
    }

#pragma unroll
    for (int mf = 0; mf < 4; mf++)
#pragma unroll
        for (int nf = 0; nf < 8; nf++) {
            int row = bm + wm + mf * 16 + gid;
            int col = bn + wn + nf * 8 + 2 * tig;
            float v0 = acc[mf][nf][0], v1 = acc[mf][nf][1];
            float v2 = acc[mf][nf][2], v3 = acc[mf][nf][3];
            if (rnd) { v0 = f2tff(v0); v1 = f2tff(v1); v2 = f2tff(v2); v3 = f2tff(v3); }
            *(float2*)&C[(size_t)row * N + col] = make_float2(v0, v1);
            *(float2*)&C[(size_t)(row + 8) * N + col] = make_float2(v2, v3);
        }
#undef ISSUE
#undef COMPUTE
}

// Merged QKV projection: grid (30, 64); v output tf32-rounded.
__global__ void __launch_bounds__(128, 3) gemm_qkv(
    const float* __restrict__ A,
    float* __restrict__ q, float* __restrict__ k, float* __restrict__ v)
{
    extern __shared__ float sd[];
    int which = blockIdx.x / 10;
    int bn = (blockIdx.x % 10) * 128;
    int bm = blockIdx.y * 128;
    const float* B = (which == 0) ? g_wq : (which == 1) ? g_wk : g_wv;
    float* C = (which == 0) ? q : (which == 1) ? k : v;
    gemm_body(A, B, C, bm, bn, E_DIM, E_DIM, sd, which == 2);
}

// Single GEMM (output projection), B = g_wo, unrounded output
__global__ void __launch_bounds__(128, 3) gemm_one(
    const float* __restrict__ A, float* __restrict__ C)
{
    extern __shared__ float sd[];
    gemm_body(A, g_wo, C, blockIdx.y * 128, blockIdx.x * 128, E_DIM, E_DIM,
              sd, false);
}

// ------------- flash attention, tf32 TC, cp.async double-buffer ----
// k, v already tf32-rounded in global -> raw 16B copies, no in-loop cvt.
#define KS_STRIDE 68
#define VS_STRIDE 72
#define ATT_STAGE_F (64 * KS_STRIDE + 64 * VS_STRIDE)   // 8960 floats
#define ATT_SMEM_BYTES (2 * ATT_STAGE_F * 4)            // 71680

__global__ void __launch_bounds__(128) attn_tf32(
    const float* __restrict__ q, const float* __restrict__ k,
    const float* __restrict__ v, float* __restrict__ o)
{
    extern __shared__ float sm[];

    int b = blockIdx.z, h = blockIdx.y, qt = blockIdx.x;
    int tid = threadIdx.x;
    int warp = tid >> 5, lane = tid & 31;
    int gid = lane >> 2, tig = lane & 3;
    int m0 = warp * 16;
    int tq0 = b * SEQ + qt * 64;

#define ATT_ISSUE(KT, S) { \
    int kt_ = (KT); int s_ = (S); \
    float* Ks_ = sm + s_ * ATT_STAGE_F; \
    float* Vs_ = Ks_ + 64 * KS_STRIDE; \
    int tk0_ = b * SEQ + kt_ * 64; \
    _Pragma("unroll") \
    for (int ii = 0; ii < 8; ii++) { \
        int idx_ = tid + ii * 128; \
        int r_ = idx_ >> 4, c4_ = (idx_ & 15) << 2; \
        const size_t goff_ = (size_t)(tk0_ + r_) * E_DIM + h * 64 + c4_; \
        cpa16(&Ks_[r_ * KS_STRIDE + c4_], &k[goff_]); \
        cpa16(&Vs_[r_ * VS_STRIDE + c4_], &v[goff_]); \
    } }

    // prologue: start tile 0, then load Q fragments while it flies
    ATT_ISSUE(0, 0); CP_COMMIT();

    unsigned qf[8][4];
    {
        const float* qp = q + (size_t)(tq0 + m0 + gid) * E_DIM + h * 64;
#pragma unroll
        for (int ks = 0; ks < 8; ks++) {
            int c = ks * 8 + tig;
            qf[ks][0] = f2tf(qp[c] * 0.125f);
            qf[ks][1] = f2tf(qp[(size_t)8 * E_DIM + c] * 0.125f);
            qf[ks][2] = f2tf(qp[c + 4] * 0.125f);
            qf[ks][3] = f2tf(qp[(size_t)8 * E_DIM + c + 4] * 0.125f);
        }
    }

    float mrow0 = -1e30f, mrow1 = -1e30f;
    float lrow0 = 0.f, lrow1 = 0.f;
    float oc[8][4];
#pragma unroll
    for (int i = 0; i < 8; i++)
#pragma unroll
        for (int j = 0; j < 4; j++) oc[i][j] = 0.f;

    for (int kt = 0; kt < SEQ / 64; kt++) {
        int cur = kt & 1;
        float* Ks = sm + cur * ATT_STAGE_F;   // K tile; becomes P after QK
        float* Vs = Ks + 64 * KS_STRIDE;

        CP_WAIT(0);          // only tile kt's group can be pending here
        __syncthreads();     // cross-thread visibility of cp.async data

        // ---- QK^T: S[16 x 64] per warp ----
        float sc[8][4];
#pragma unroll
        for (int i = 0; i < 8; i++)
#pragma unroll
            for (int j = 0; j < 4; j++) sc[i][j] = 0.f;
#pragma unroll
        for (int ks = 0; ks < 8; ks++) {
#pragma unroll
            for (int nf = 0; nf < 8; nf++) {
                int bb = (nf * 8 + gid) * KS_STRIDE + ks * 8 + tig;
                unsigned b0 = __float_as_uint(Ks[bb]);
                unsigned b1 = __float_as_uint(Ks[bb + 4]);
                mma_tf32(sc[nf], qf[ks], b0, b1);
            }
        }
        __syncthreads();     // all warps done reading Ks -> safe to write P

        // ---- online softmax ----
        float tm0 = -1e30f, tm1 = -1e30f;
#pragma unroll
        for (int nf = 0; nf < 8; nf++) {
            tm0 = fmaxf(tm0, fmaxf(sc[nf][0], sc[nf][1]));
            tm1 = fmaxf(tm1, fmaxf(sc[nf][2], sc[nf][3]));
        }
        tm0 = fmaxf(tm0, __shfl_xor_sync(0xffffffffu, tm0, 1));
        tm0 = fmaxf(tm0, __shfl_xor_sync(0xffffffffu, tm0, 2));
        tm1 = fmaxf(tm1, __shfl_xor_sync(0xffffffffu, tm1, 1));
        tm1 = fmaxf(tm1, __shfl_xor_sync(0xffffffffu, tm1, 2));
        float mn0 = fmaxf(mrow0, tm0), mn1 = fmaxf(mrow1, tm1);
        float cor0 = __expf(mrow0 - mn0), cor1 = __expf(mrow1 - mn1);
        float ls0 = 0.f, ls1 = 0.f;
#pragma unroll
        for (int nf = 0; nf < 8; nf++) {
            float p0 = __expf(sc[nf][0] - mn0);
            float p1 = __expf(sc[nf][1] - mn0);
            float p2 = __expf(sc[nf][2] - mn1);
            float p3 = __expf(sc[nf][3] - mn1);
            ls0 += p0 + p1; ls1 += p2 + p3;
            int pb = (m0 + gid) * KS_STRIDE + nf * 8 + 2 * tig;
            *(float2*)&Ks[pb] = make_float2(f2tff(p0), f2tff(p1));
            *(float2*)&Ks[pb + 8 * KS_STRIDE] = make_float2(f2tff(p2), f2tff(p3));
        }
        ls0 += __shfl_xor_sync(0xffffffffu, ls0, 1);
        ls0 += __shfl_xor_sync(0xffffffffu, ls0, 2);
        ls1 += __shfl_xor_sync(0xffffffffu, ls1, 1);
        ls1 += __shfl_xor_sync(0xffffffffu, ls1, 2);
        lrow0 = lrow0 * cor0 + ls0;
        lrow1 = lrow1 * cor1 + ls1;
        mrow0 = mn0; mrow1 = mn1;
#pragma unroll
        for (int nf = 0; nf < 8; nf++) {
            oc[nf][0] *= cor0; oc[nf][1] *= cor0;
            oc[nf][2] *= cor1; oc[nf][3] *= cor1;
        }
        __syncwarp();   // P visible to own warp (PV reads own 16 rows only)

        // ---- PV: O[16 x 64] += P[16 x 64k] * V[64k x 64] ----
#pragma unroll
        for (int ks = 0; ks < 8; ks++) {
            unsigned af[4];
            int ab = (m0 + gid) * KS_STRIDE + ks * 8 + tig;
            af[0] = __float_as_uint(Ks[ab]);
            af[1] = __float_as_uint(Ks[ab + 8 * KS_STRIDE]);
            af[2] = __float_as_uint(Ks[ab + 4]);
            af[3] = __float_as_uint(Ks[ab + 8 * KS_STRIDE + 4]);
#pragma unroll
            for (int nf = 0; nf < 8; nf++) {
                int vb = (ks * 8 + tig) * VS_STRIDE + nf * 8 + gid;
                unsigned b0 = __float_as_uint(Vs[vb]);
                unsigned b1 = __float_as_uint(Vs[vb + 4 * VS_STRIDE]);
                mma_tf32(oc[nf], af, b0, b1);
            }
        }

        // prefetch next tile into the other buffer. That buffer was last
        // read in iteration kt-1; every warp passed the top-of-kt barrier
        // (after its PV of kt-1), so WAR-safe.
        if (kt + 1 < SEQ / 64) { ATT_ISSUE(kt + 1, 1 - cur); }
        CP_COMMIT();
    }

    // o written tf32-rounded -> Wout GEMM reads raw bits
    float il0 = 1.f / lrow0, il1 = 1.f / lrow1;
    int row = tq0 + m0 + gid;
#pragma unroll
    for (int nf = 0; nf < 8; nf++) {
        int col = h * 64 + nf * 8 + 2 * tig;
        *(float2*)&o[(size_t)row * E_DIM + col] =
            make_float2(f2tff(oc[nf][0] * il0), f2tff(oc[nf][1] * il0));
        *(float2*)&o[(size_t)(row + 8) * E_DIM + col] =
            make_float2(f2tff(oc[nf][2] * il1), f2tff(oc[nf][3] * il1));
    }
#undef ATT_ISSUE
}

// -------------------------------------------------------------------
extern "C" void kernel_launch(void* const* d_in, const int* in_sizes, int n_in,
                              void* d_out, int out_size)
{
    const float* x  = (const float*)d_in[0];
    const int*   cu = (const int*)d_in[1];
    int idx = 2;
    if (in_sizes[2] == 1) idx = 3;  // skip scalar max_len if present
    const float* norm_w = (const float*)d_in[idx++];
    const float* norm_b = (const float*)d_in[idx++];
    const float* Wq     = (const float*)d_in[idx++];
    const float* Wk     = (const float*)d_in[idx++];
    const float* Wv     = (const float*)d_in[idx++];
    const float* Wout   = (const float*)d_in[idx++];
    const float* lnq_w  = (const float*)d_in[idx++];
    const float* lnk_w  = (const float*)d_in[idx++];
    float* out = (float*)d_out;

    int nb = in_sizes[1] - 1;

    float *h, *q, *k, *v, *o;
    cudaGetSymbolAddress((void**)&h, g_h);
    cudaGetSymbolAddress((void**)&q, g_q);
    cudaGetSymbolAddress((void**)&k, g_k);
    cudaGetSymbolAddress((void**)&v, g_v);
    cudaGetSymbolAddress((void**)&o, g_o);

    // opt-in dynamic smem (host-side attribute sets; not stream ops)
    cudaFuncSetAttribute(gemm_qkv, cudaFuncAttributeMaxDynamicSharedMemorySize,
                         GEMM_SMEM_BYTES);
    cudaFuncSetAttribute(gemm_one, cudaFuncAttributeMaxDynamicSharedMemorySize,
                         GEMM_SMEM_BYTES);
    cudaFuncSetAttribute(attn_tf32, cudaFuncAttributeMaxDynamicSharedMemorySize,
                         ATT_SMEM_BYTES);

    // 0) round weights to tf32 once per call
    wprep_kernel<<<dim3(E_DIM * E_DIM / 1024, 4), 256>>>(Wq, Wk, Wv, Wout);

    // 1) pre-norm (tf32-rounded output) + rope table
    ln_kernel<<<T_TOK, 256>>>(x, norm_w, norm_b, h);
    rope_table_kernel<<<T_TOK / 8, 256>>>(cu, nb);

    // 2) merged Q/K/V projections (3-stage pipeline, 3 CTAs/SM)
    gemm_qkv<<<dim3(30, T_TOK / 128), 128, GEMM_SMEM_BYTES>>>(h, q, k, v);

    // 3) q/k LayerNorm + RoPE (in place, rounded output)
    lnrope_kernel<<<dim3(T_TOK, 2), 256>>>(q, k, lnq_w, lnk_w);

    // 4) attention (double-buffered K/V, rounded o output)
    dim3 agrid(SEQ / 64, NHEAD, NBATCH);
    attn_tf32<<<agrid, 128, ATT_SMEM_BYTES>>>(q, k, v, o);

    // 5) output projection
    gemm_one<<<dim3(E_DIM / 128, T_TOK / 128), 128, GEMM_SMEM_BYTES>>>(o, out);
}

// round 12
// speedup vs baseline: 7.6231x; 1.0242x over previous
#include <cuda_runtime.h>
#include <math.h>

#define E_DIM 1280
#define NHEAD 20
#define DHEAD 64
#define T_TOK 8192
#define SEQ   1024
#define NBATCH 8

// ---------------- scratch (no allocations allowed) ----------------
__device__ float g_h[T_TOK * E_DIM];
__device__ float g_q[T_TOK * E_DIM];
__device__ float g_k[T_TOK * E_DIM];
__device__ float g_v[T_TOK * E_DIM];
__device__ float g_o[T_TOK * E_DIM];
__device__ float g_wq[E_DIM * E_DIM];
__device__ float g_wk[E_DIM * E_DIM];
__device__ float g_wv[E_DIM * E_DIM];
__device__ float g_wo[E_DIM * E_DIM];
__device__ float g_cos[T_TOK * 32];
__device__ float g_sin[T_TOK * 32];

// ---------------- helpers ----------------
__device__ __forceinline__ unsigned f2tf(float f) {
    unsigned u;
    asm("cvt.rna.tf32.f32 %0, %1;" : "=r"(u) : "f"(f));
    return u;
}
__device__ __forceinline__ float f2tff(float f) {
    return __uint_as_float(f2tf(f));
}

__device__ __forceinline__ void mma_tf32(float c[4], const unsigned a[4],
                                         unsigned b0, unsigned b1) {
    asm volatile(
        "mma.sync.aligned.m16n8k8.row.col.f32.tf32.tf32.f32 "
        "{%0,%1,%2,%3}, {%4,%5,%6,%7}, {%8,%9}, {%0,%1,%2,%3};\n"
        : "+f"(c[0]), "+f"(c[1]), "+f"(c[2]), "+f"(c[3])
        : "r"(a[0]), "r"(a[1]), "r"(a[2]), "r"(a[3]), "r"(b0), "r"(b1));
}

__device__ __forceinline__ void cpa16(void* s, const void* g) {
    unsigned saddr = (unsigned)__cvta_generic_to_shared(s);
    asm volatile("cp.async.ca.shared.global [%0], [%1], 16;\n"
                 :: "r"(saddr), "l"(g));
}
#define CP_COMMIT() asm volatile("cp.async.commit_group;\n" ::: "memory")
#define CP_WAIT(N)  asm volatile("cp.async.wait_group " #N ";\n" ::: "memory")

// ------------- weight prep: round to tf32 in global ---------------
__global__ void __launch_bounds__(256) wprep_kernel(
    const float* __restrict__ Wq, const float* __restrict__ Wk,
    const float* __restrict__ Wv, const float* __restrict__ Wo)
{
    const float* src = (blockIdx.y == 0) ? Wq : (blockIdx.y == 1) ? Wk :
                       (blockIdx.y == 2) ? Wv : Wo;
    float* dst = (blockIdx.y == 0) ? g_wq : (blockIdx.y == 1) ? g_wk :
                 (blockIdx.y == 2) ? g_wv : g_wo;
    int i = (blockIdx.x * 256 + threadIdx.x) * 4;
    float4 v = *(const float4*)&src[i];
    *(float4*)&dst[i] = make_float4(f2tff(v.x), f2tff(v.y), f2tff(v.z), f2tff(v.w));
}

// ---------------- LayerNorm (with bias) : x -> h (tf32-rounded) ----
__global__ void __launch_bounds__(256) ln_kernel(
    const float* __restrict__ x, const float* __restrict__ w,
    const float* __restrict__ b, float* __restrict__ out)
{
    int t = blockIdx.x;
    const float* xr = x + (size_t)t * E_DIM;
    float vals[5];
    float s = 0.f, s2 = 0.f;
#pragma unroll
    for (int j = 0; j < 5; j++) {
        float v = xr[threadIdx.x + j * 256];
        vals[j] = v; s += v; s2 += v * v;
    }
    __shared__ float red0[8], red1[8];
    int lane = threadIdx.x & 31, wid = threadIdx.x >> 5;
#pragma unroll
    for (int o = 16; o; o >>= 1) {
        s  += __shfl_xor_sync(0xffffffffu, s,  o);
        s2 += __shfl_xor_sync(0xffffffffu, s2, o);
    }
    if (lane == 0) { red0[wid] = s; red1[wid] = s2; }
    __syncthreads();
    float ts = 0.f, ts2 = 0.f;
#pragma unroll
    for (int j = 0; j < 8; j++) { ts += red0[j]; ts2 += red1[j]; }
    float mean = ts * (1.f / E_DIM);
    float var  = ts2 * (1.f / E_DIM) - mean * mean;
    float rstd = rsqrtf(var + 1e-5f);
    float* orow = out + (size_t)t * E_DIM;
#pragma unroll
    for (int j = 0; j < 5; j++) {
        int idx = threadIdx.x + j * 256;
        orow[idx] = f2tff((vals[j] - mean) * rstd * w[idx] + b[idx]);
    }
}

// ---------------- RoPE table: cos/sin per (token, freq) ------------
__global__ void __launch_bounds__(256) rope_table_kernel(
    const int* __restrict__ cu, int nb)
{
    int t = blockIdx.x * 8 + (threadIdx.x >> 5);
    int f = threadIdx.x & 31;
    int seg = 0;
    for (int bb = 1; bb < nb; bb++) if (t >= cu[bb]) seg = bb;
    float pos = (float)(t - cu[seg]);
    const float kfreq = -0.2878231366f; // -ln(10000)/32
    float ang = pos * __expf((float)f * kfreq);
    float sn, c;
    sincosf(ang, &sn, &c);
    g_cos[t * 32 + f] = c;
    g_sin[t * 32 + f] = sn;
}

// ------------- LayerNorm (no bias) + RoPE, in place (rounded) ------
__global__ void __launch_bounds__(256) lnrope_kernel(
    float* __restrict__ q, float* __restrict__ k,
    const float* __restrict__ wq, const float* __restrict__ wk)
{
    int t = blockIdx.x;
    int part = blockIdx.y;
    __shared__ float sb[E_DIM];
    __shared__ float red0[8], red1[8];
    __shared__ float s_stats[2];
    int lane = threadIdx.x & 31, wid = threadIdx.x >> 5;

    float* base = (part ? k : q) + (size_t)t * E_DIM;
    const float* w = part ? wk : wq;
    float s = 0.f, s2 = 0.f;
    for (int i = threadIdx.x; i < E_DIM; i += 256) {
        float v = base[i];
        sb[i] = v; s += v; s2 += v * v;
    }
#pragma unroll
    for (int o = 16; o; o >>= 1) {
        s  += __shfl_xor_sync(0xffffffffu, s,  o);
        s2 += __shfl_xor_sync(0xffffffffu, s2, o);
    }
    if (lane == 0) { red0[wid] = s; red1[wid] = s2; }
    __syncthreads();
    if (threadIdx.x == 0) {
        float ts = 0.f, ts2 = 0.f;
#pragma unroll
        for (int j = 0; j < 8; j++) { ts += red0[j]; ts2 += red1[j]; }
        float mean = ts * (1.f / E_DIM);
        float var  = ts2 * (1.f / E_DIM) - mean * mean;
        s_stats[0] = mean;
        s_stats[1] = rsqrtf(var + 1e-5f);
    }
    __syncthreads();
    float mean = s_stats[0], rstd = s_stats[1];
    for (int i = threadIdx.x; i < E_DIM; i += 256) {
        int ld = i & 63;
        float xn = (sb[i] - mean) * rstd * w[i];
        int pi = (ld < 32) ? (i + 32) : (i - 32);
        float pn = (sb[pi] - mean) * rstd * w[pi];
        int fi = ld & 31;
        float c  = g_cos[t * 32 + fi];
        float sn = g_sin[t * 32 + fi];
        float rot = (ld < 32) ? -pn : pn;
        base[i] = f2tff(xn * c + rot * sn);
    }
}

// ------------- tf32 GEMM core, 3-stage cp.async pipeline -----------
// 128 threads (4 warps, 2x2), warp tile 64x64, 3 CTAs/SM. (unchanged R10)
#define GSTR 20
#define GSTAGE_F (2 * 128 * GSTR)            // floats per stage (A then B)
#define GEMM_SMEM_BYTES (3 * GSTAGE_F * 4)   // 61440

__device__ __forceinline__ void gemm_body(
    const float* __restrict__ A, const float* __restrict__ B,
    float* __restrict__ C, int bm, int bn, int N, int K,
    float* sd, bool rnd)
{
    int tid = threadIdx.x, lane = tid & 31, warp = tid >> 5;
    int gid = lane >> 2, tig = lane & 3;
    int wm = (warp >> 1) * 64, wn = (warp & 1) * 64;

    float acc[4][8][4];
#pragma unroll
    for (int i = 0; i < 4; i++)
#pragma unroll
        for (int j = 0; j < 8; j++)
#pragma unroll
            for (int l = 0; l < 4; l++) acc[i][j][l] = 0.f;

    int lr = tid >> 2;           // 0..31
    int lc = (tid & 3) << 2;     // 0,4,8,12
    const float* Ap = A + (size_t)(bm + lr) * K + lc;
    const float* Bp = B + (size_t)(bn + lr) * K + lc;

#define ISSUE(S, K0) { \
    int s_ = (S); int k0_ = (K0); \
    float* As_ = sd + s_ * GSTAGE_F; \
    float* Bs_ = As_ + 128 * GSTR; \
    _Pragma("unroll") \
    for (int ii = 0; ii < 4; ii++) { \
        int row = lr + ii * 32; \
        cpa16(&As_[row * GSTR + lc], Ap + (size_t)ii * 32 * K + k0_); \
        cpa16(&Bs_[row * GSTR + lc], Bp + (size_t)ii * 32 * K + k0_); \
    } }

#define COMPUTE(S) { \
    const float* Asb = sd + (S) * GSTAGE_F; \
    const float* Bsb = Asb + 128 * GSTR; \
    _Pragma("unroll") \
    for (int ks = 0; ks < 2; ks++) { \
        unsigned af[4][4]; \
        _Pragma("unroll") \
        for (int mf = 0; mf < 4; mf++) { \
            int base = (wm + mf * 16 + gid) * GSTR + ks * 8 + tig; \
            af[mf][0] = __float_as_uint(Asb[base]); \
            af[mf][1] = __float_as_uint(Asb[base + 8 * GSTR]); \
            af[mf][2] = __float_as_uint(Asb[base + 4]); \
            af[mf][3] = __float_as_uint(Asb[base + 8 * GSTR + 4]); \
        } \
        _Pragma("unroll") \
        for (int nf = 0; nf < 8; nf++) { \
            int bb = (wn + nf * 8 + gid) * GSTR + ks * 8 + tig; \
            unsigned b0 = __float_as_uint(Bsb[bb]); \
            unsigned b1 = __float_as_uint(Bsb[bb + 4]); \
            mma_tf32(acc[0][nf], af[0], b0, b1); \
            mma_tf32(acc[1][nf], af[1], b0, b1); \
            mma_tf32(acc[2][nf], af[2], b0, b1); \
            mma_tf32(acc[3][nf], af[3], b0, b1); \
        } \
    } }

    int NT = K / 16;   // 80
    ISSUE(0, 0);  CP_COMMIT();
    ISSUE(1, 16); CP_COMMIT();
    int cs = 0;        // compute stage = i % 3
    for (int i = 0; i < NT; i++) {
        CP_WAIT(1);
        __syncthreads();
        COMPUTE(cs);
        // stage (i+2)%3 == (i-1)%3 was last read in compute(i-1);
        // the barrier above guarantees all warps finished it.
        if (i + 2 < NT) {
            int ns = cs - 1; if (ns < 0) ns = 2;   // (i+2)%3
            ISSUE(ns, (i + 2) * 16);
        }
        CP_COMMIT();   // empty groups at tail keep the wait count uniform
        cs = (cs == 2) ? 0 : cs + 1;
    }

#pragma unroll
    for (int mf = 0; mf < 4; mf++)
#pragma unroll
        for (int nf = 0; nf < 8; nf++) {
            int row = bm + wm + mf * 16 + gid;
            int col = bn + wn + nf * 8 + 2 * tig;
            float v0 = acc[mf][nf][0], v1 = acc[mf][nf][1];
            float v2 = acc[mf][nf][2], v3 = acc[mf][nf][3];
            if (rnd) { v0 = f2tff(v0); v1 = f2tff(v1); v2 = f2tff(v2); v3 = f2tff(v3); }
            *(float2*)&C[(size_t)row * N + col] = make_float2(v0, v1);
            *(float2*)&C[(size_t)(row + 8) * N + col] = make_float2(v2, v3);
        }
#undef ISSUE
#undef COMPUTE
}

// Merged QKV projection: grid (30, 64); v output tf32-rounded.
__global__ void __launch_bounds__(128, 3) gemm_qkv(
    const float* __restrict__ A,
    float* __restrict__ q, float* __restrict__ k, float* __restrict__ v)
{
    extern __shared__ float sd[];
    int which = blockIdx.x / 10;
    int bn = (blockIdx.x % 10) * 128;
    int bm = blockIdx.y * 128;
    const float* B = (which == 0) ? g_wq : (which == 1) ? g_wk : g_wv;
    float* C = (which == 0) ? q : (which == 1) ? k : v;
    gemm_body(A, B, C, bm, bn, E_DIM, E_DIM, sd, which == 2);
}

// Single GEMM (output projection), B = g_wo, unrounded output
__global__ void __launch_bounds__(128, 3) gemm_one(
    const float* __restrict__ A, float* __restrict__ C)
{
    extern __shared__ float sd[];
    gemm_body(A, g_wo, C, blockIdx.y * 128, blockIdx.x * 128, E_DIM, E_DIM,
              sd, false);
}

// ------------- flash attention, tf32 TC, cp.async double-buffer ----
// 128 q-rows per CTA, 4 warps x 32 rows (2 m16 fragments/warp): K/V
// smem reads amortize over 2x the MMAs vs R10 (crossbar-bound fix).
// P has its own buffer (no K aliasing) -> one barrier per kt tile.
#define KS_STRIDE 68
#define VS_STRIDE 72
#define PS_STRIDE 68
#define ATT_STAGE_F (64 * KS_STRIDE + 64 * VS_STRIDE)   // 8960 floats
#define ATT_P_F (128 * PS_STRIDE)                        // 8704 floats
#define ATT_SMEM_BYTES ((2 * ATT_STAGE_F + ATT_P_F) * 4) // 106496

__global__ void __launch_bounds__(128) attn_tf32(
    const float* __restrict__ q, const float* __restrict__ k,
    const float* __restrict__ v, float* __restrict__ o)
{
    extern __shared__ float sm[];
    float* PS = sm + 2 * ATT_STAGE_F;

    int b = blockIdx.z, h = blockIdx.y, qt = blockIdx.x;
    int tid = threadIdx.x;
    int warp = tid >> 5, lane = tid & 31;
    int gid = lane >> 2, tig = lane & 3;
    int m0 = warp * 32;
    int tq0 = b * SEQ + qt * 128;

#define ATT_ISSUE(KT, S) { \
    int kt_ = (KT); int s_ = (S); \
    float* Ks_ = sm + s_ * ATT_STAGE_F; \
    float* Vs_ = Ks_ + 64 * KS_STRIDE; \
    int tk0_ = b * SEQ + kt_ * 64; \
    _Pragma("unroll") \
    for (int ii = 0; ii < 8; ii++) { \
        int idx_ = tid + ii * 128; \
        int r_ = idx_ >> 4, c4_ = (idx_ & 15) << 2; \
        const size_t goff_ = (size_t)(tk0_ + r_) * E_DIM + h * 64 + c4_; \
        cpa16(&Ks_[r_ * KS_STRIDE + c4_], &k[goff_]); \
        cpa16(&Vs_[r_ * VS_STRIDE + c4_], &v[goff_]); \
    } }

    // prologue: start tile 0, then load Q fragments while it flies
    ATT_ISSUE(0, 0); CP_COMMIT();

    unsigned qf[8][2][4];
#pragma unroll
    for (int mf = 0; mf < 2; mf++) {
        const float* qp = q + (size_t)(tq0 + m0 + mf * 16 + gid) * E_DIM + h * 64;
#pragma unroll
        for (int ks = 0; ks < 8; ks++) {
            int c = ks * 8 + tig;
            qf[ks][mf][0] = f2tf(qp[c] * 0.125f);
            qf[ks][mf][1] = f2tf(qp[(size_t)8 * E_DIM + c] * 0.125f);
            qf[ks][mf][2] = f2tf(qp[c + 4] * 0.125f);
            qf[ks][mf][3] = f2tf(qp[(size_t)8 * E_DIM + c + 4] * 0.125f);
        }
    }

    float mrow[2][2], lrow[2][2];
#pragma unroll
    for (int mf = 0; mf < 2; mf++) {
        mrow[mf][0] = -1e30f; mrow[mf][1] = -1e30f;
        lrow[mf][0] = 0.f;    lrow[mf][1] = 0.f;
    }
    float oc[2][8][4];
#pragma unroll
    for (int mf = 0; mf < 2; mf++)
#pragma unroll
        for (int j = 0; j < 8; j++)
#pragma unroll
            for (int l = 0; l < 4; l++) oc[mf][j][l] = 0.f;

    for (int kt = 0; kt < SEQ / 64; kt++) {
        int cur = kt & 1;
        float* Ks = sm + cur * ATT_STAGE_F;
        float* Vs = Ks + 64 * KS_STRIDE;

        CP_WAIT(0);          // tile kt landed
        __syncthreads();     // visibility + WAR fence for this buffer

        // ---- QK^T: S[32 x 64] per warp ----
        float sc[2][8][4];
#pragma unroll
        for (int mf = 0; mf < 2; mf++)
#pragma unroll
            for (int j = 0; j < 8; j++)
#pragma unroll
                for (int l = 0; l < 4; l++) sc[mf][j][l] = 0.f;
#pragma unroll
        for (int ks = 0; ks < 8; ks++) {
#pragma unroll
            for (int nf = 0; nf < 8; nf++) {
                int bb = (nf * 8 + gid) * KS_STRIDE + ks * 8 + tig;
                unsigned b0 = __float_as_uint(Ks[bb]);
                unsigned b1 = __float_as_uint(Ks[bb + 4]);
                mma_tf32(sc[0][nf], qf[ks][0], b0, b1);
                mma_tf32(sc[1][nf], qf[ks][1], b0, b1);
            }
        }

        // ---- online softmax (per mf fragment) ----
#pragma unroll
        for (int mf = 0; mf < 2; mf++) {
            float tm0 = -1e30f, tm1 = -1e30f;
#pragma unroll
            for (int nf = 0; nf < 8; nf++) {
                tm0 = fmaxf(tm0, fmaxf(sc[mf][nf][0], sc[mf][nf][1]));
                tm1 = fmaxf(tm1, fmaxf(sc[mf][nf][2], sc[mf][nf][3]));
            }
            tm0 = fmaxf(tm0, __shfl_xor_sync(0xffffffffu, tm0, 1));
            tm0 = fmaxf(tm0, __shfl_xor_sync(0xffffffffu, tm0, 2));
            tm1 = fmaxf(tm1, __shfl_xor_sync(0xffffffffu, tm1, 1));
            tm1 = fmaxf(tm1, __shfl_xor_sync(0xffffffffu, tm1, 2));
            float mn0 = fmaxf(mrow[mf][0], tm0), mn1 = fmaxf(mrow[mf][1], tm1);
            float cor0 = __expf(mrow[mf][0] - mn0);
            float cor1 = __expf(mrow[mf][1] - mn1);
            float ls0 = 0.f, ls1 = 0.f;
#pragma unroll
            for (int nf = 0; nf < 8; nf++) {
                float p0 = __expf(sc[mf][nf][0] - mn0);
                float p1 = __expf(sc[mf][nf][1] - mn0);
                float p2 = __expf(sc[mf][nf][2] - mn1);
                float p3 = __expf(sc[mf][nf][3] - mn1);
                ls0 += p0 + p1; ls1 += p2 + p3;
                int pb = (m0 + mf * 16 + gid) * PS_STRIDE + nf * 8 + 2 * tig;
                *(float2*)&PS[pb] = make_float2(f2tff(p0), f2tff(p1));
                *(float2*)&PS[pb + 8 * PS_STRIDE] = make_float2(f2tff(p2), f2tff(p3));
            }
            ls0 += __shfl_xor_sync(0xffffffffu, ls0, 1);
            ls0 += __shfl_xor_sync(0xffffffffu, ls0, 2);
            ls1 += __shfl_xor_sync(0xffffffffu, ls1, 1);
            ls1 += __shfl_xor_sync(0xffffffffu, ls1, 2);
            lrow[mf][0] = lrow[mf][0] * cor0 + ls0;
            lrow[mf][1] = lrow[mf][1] * cor1 + ls1;
            mrow[mf][0] = mn0; mrow[mf][1] = mn1;
#pragma unroll
            for (int nf = 0; nf < 8; nf++) {
                oc[mf][nf][0] *= cor0; oc[mf][nf][1] *= cor0;
                oc[mf][nf][2] *= cor1; oc[mf][nf][3] *= cor1;
            }
        }
        __syncwarp();   // P visible to own warp (PV reads own 32 rows only)

        // ---- PV: O[32 x 64] += P[32 x 64k] * V[64k x 64] ----
#pragma unroll
        for (int ks = 0; ks < 8; ks++) {
            unsigned af[2][4];
#pragma unroll
            for (int mf = 0; mf < 2; mf++) {
                int ab = (m0 + mf * 16 + gid) * PS_STRIDE + ks * 8 + tig;
                af[mf][0] = __float_as_uint(PS[ab]);
                af[mf][1] = __float_as_uint(PS[ab + 8 * PS_STRIDE]);
                af[mf][2] = __float_as_uint(PS[ab + 4]);
                af[mf][3] = __float_as_uint(PS[ab + 8 * PS_STRIDE + 4]);
            }
#pragma unroll
            for (int nf = 0; nf < 8; nf++) {
                int vb = (ks * 8 + tig) * VS_STRIDE + nf * 8 + gid;
                unsigned b0 = __float_as_uint(Vs[vb]);
                unsigned b1 = __float_as_uint(Vs[vb + 4 * VS_STRIDE]);
                mma_tf32(oc[0][nf], af[0], b0, b1);
                mma_tf32(oc[1][nf], af[1], b0, b1);
            }
        }

        // prefetch next tile into the other buffer: all warps passed the
        // top-of-kt barrier, so their kt-1 reads of that buffer are done.
        if (kt + 1 < SEQ / 64) { ATT_ISSUE(kt + 1, 1 - cur); }
        CP_COMMIT();
    }

    // o written tf32-rounded -> Wout GEMM reads raw bits
#pragma unroll
    for (int mf = 0; mf < 2; mf++) {
        float il0 = 1.f / lrow[mf][0], il1 = 1.f / lrow[mf][1];
        int row = tq0 + m0 + mf * 16 + gid;
#pragma unroll
        for (int nf = 0; nf < 8; nf++) {
            int col = h * 64 + nf * 8 + 2 * tig;
            *(float2*)&o[(size_t)row * E_DIM + col] =
                make_float2(f2tff(oc[mf][nf][0] * il0), f2tff(oc[mf][nf][1] * il0));
            *(float2*)&o[(size_t)(row + 8) * E_DIM + col] =
                make_float2(f2tff(oc[mf][nf][2] * il1), f2tff(oc[mf][nf][3] * il1));
        }
    }
#undef ATT_ISSUE
}

// -------------------------------------------------------------------
extern "C" void kernel_launch(void* const* d_in, const int* in_sizes, int n_in,
                              void* d_out, int out_size)
{
    const float* x  = (const float*)d_in[0];
    const int*   cu = (const int*)d_in[1];
    int idx = 2;
    if (in_sizes[2] == 1) idx = 3;  // skip scalar max_len if present
    const float* norm_w = (const float*)d_in[idx++];
    const float* norm_b = (const float*)d_in[idx++];
    const float* Wq     = (const float*)d_in[idx++];
    const float* Wk     = (const float*)d_in[idx++];
    const float* Wv     = (const float*)d_in[idx++];
    const float* Wout   = (const float*)d_in[idx++];
    const float* lnq_w  = (const float*)d_in[idx++];
    const float* lnk_w  = (const float*)d_in[idx++];
    float* out = (float*)d_out;

    int nb = in_sizes[1] - 1;

    float *h, *q, *k, *v, *o;
    cudaGetSymbolAddress((void**)&h, g_h);
    cudaGetSymbolAddress((void**)&q, g_q);
    cudaGetSymbolAddress((void**)&k, g_k);
    cudaGetSymbolAddress((void**)&v, g_v);
    cudaGetSymbolAddress((void**)&o, g_o);

    // opt-in dynamic smem (host-side attribute sets; not stream ops)
    cudaFuncSetAttribute(gemm_qkv, cudaFuncAttributeMaxDynamicSharedMemorySize,
                         GEMM_SMEM_BYTES);
    cudaFuncSetAttribute(gemm_one, cudaFuncAttributeMaxDynamicSharedMemorySize,
                         GEMM_SMEM_BYTES);
    cudaFuncSetAttribute(attn_tf32, cudaFuncAttributeMaxDynamicSharedMemorySize,
                         ATT_SMEM_BYTES);

    // 0) round weights to tf32 once per call
    wprep_kernel<<<dim3(E_DIM * E_DIM / 1024, 4), 256>>>(Wq, Wk, Wv, Wout);

    // 1) pre-norm (tf32-rounded output) + rope table
    ln_kernel<<<T_TOK, 256>>>(x, norm_w, norm_b, h);
    rope_table_kernel<<<T_TOK / 8, 256>>>(cu, nb);

    // 2) merged Q/K/V projections (3-stage pipeline, 3 CTAs/SM)
    gemm_qkv<<<dim3(30, T_TOK / 128), 128, GEMM_SMEM_BYTES>>>(h, q, k, v);

    // 3) q/k LayerNorm + RoPE (in place, rounded output)
    lnrope_kernel<<<dim3(T_TOK, 2), 256>>>(q, k, lnq_w, lnk_w);

    // 4) attention (128 q-rows/CTA, double-buffered K/V)
    dim3 agrid(SEQ / 128, NHEAD, NBATCH);
    attn_tf32<<<agrid, 128, ATT_SMEM_BYTES>>>(q, k, v, o);

    // 5) output projection
    gemm_one<<<dim3(E_DIM / 128, T_TOK / 128), 128, GEMM_SMEM_BYTES>>>(o, out);
}